// round 5
// baseline (speedup 1.0000x reference)
#include <cuda_runtime.h>

#define B_   4
#define S_   2048
#define D_   1024
#define H_   16
#define HD   64
#define ROWS (B_*S_)          // 8192
#define NEG_BIG (-1e9f)

// Scratch (allocation-free): 4 x 32MB in module .bss
__device__ float g_Qh[(size_t)B_*H_*S_*HD];
__device__ float g_Kh[(size_t)B_*H_*S_*HD];
__device__ float g_Vh[(size_t)B_*H_*S_*HD];
__device__ float g_ctx[(size_t)ROWS*D_];

// ---------------------------------------------------------------------------
// Fused QKV projection: O = X @ W^T  (X [8192,1024], W [1024,1024] row-major,
// inner dim contiguous in both => NT gemm). Epilogue remaps to [b,h,s,hd]
// and folds the 1/sqrt(64) scale into Q.
// 64x64 tile, BK=16, 16x16 threads, 4x4 per thread.
// ---------------------------------------------------------------------------
__global__ __launch_bounds__(256) void proj_kernel(
    const float* __restrict__ Xq, const float* __restrict__ Xk, const float* __restrict__ Xv,
    const float* __restrict__ Wq, const float* __restrict__ Wk, const float* __restrict__ Wv)
{
    __shared__ float As[16][68];
    __shared__ float Bs[16][68];

    const int z = blockIdx.z;
    const float* X = (z == 0) ? Xq : ((z == 1) ? Xk : Xv);
    const float* W = (z == 0) ? Wq : ((z == 1) ? Wk : Wv);
    float*       O = (z == 0) ? g_Qh : ((z == 1) ? g_Kh : g_Vh);
    const float scale = (z == 0) ? 0.125f : 1.0f;

    const int m0 = blockIdx.y * 64;
    const int n0 = blockIdx.x * 64;
    const int t  = threadIdx.x;
    const int tx = t & 15, ty = t >> 4;
    const int lr = t >> 2, lq = t & 3;    // loader: row-in-tile, float4-in-row

    float acc[4][4];
#pragma unroll
    for (int r = 0; r < 4; r++)
#pragma unroll
        for (int c = 0; c < 4; c++) acc[r][c] = 0.f;

    const float* Ap = X + (size_t)(m0 + lr) * D_ + lq * 4;
    const float* Bp = W + (size_t)(n0 + lr) * D_ + lq * 4;

    for (int kt = 0; kt < D_; kt += 16) {
        float4 a = *(const float4*)(Ap + kt);
        float4 b = *(const float4*)(Bp + kt);
        __syncthreads();
        As[lq * 4 + 0][lr] = a.x; As[lq * 4 + 1][lr] = a.y;
        As[lq * 4 + 2][lr] = a.z; As[lq * 4 + 3][lr] = a.w;
        Bs[lq * 4 + 0][lr] = b.x; Bs[lq * 4 + 1][lr] = b.y;
        Bs[lq * 4 + 2][lr] = b.z; Bs[lq * 4 + 3][lr] = b.w;
        __syncthreads();
#pragma unroll
        for (int kk = 0; kk < 16; kk++) {
            float4 av = *(const float4*)&As[kk][ty * 4];
            float4 bv = *(const float4*)&Bs[kk][tx * 4];
            float aa[4] = {av.x, av.y, av.z, av.w};
            float bb[4] = {bv.x, bv.y, bv.z, bv.w};
#pragma unroll
            for (int r = 0; r < 4; r++)
#pragma unroll
                for (int c = 0; c < 4; c++) acc[r][c] += aa[r] * bb[c];
        }
    }

    const int h = n0 >> 6;   // tile spans exactly one head
#pragma unroll
    for (int r = 0; r < 4; r++) {
        int row = m0 + ty * 4 + r;
        int bb  = row >> 11;        // / 2048
        int s   = row & 2047;
        float4 o = make_float4(acc[r][0] * scale, acc[r][1] * scale,
                               acc[r][2] * scale, acc[r][3] * scale);
        *(float4*)&O[((size_t)(bb * H_ + h) * S_ + s) * HD + tx * 4] = o;
    }
}

// ---------------------------------------------------------------------------
// Flash attention. One block = (b,h, 64-query tile). KV loop capped at
// min(q0+64, sen_len[b]) — keys >= sen_len are masked for every query, and
// j=0 is always valid (sen_len >= 1), so clipping is numerically exact.
// Dynamic smem: QsT[64d][68] | KsT/PsT[64][68] | Vs[64k][68] = 52224 B.
// ---------------------------------------------------------------------------
__global__ __launch_bounds__(256) void attn_kernel(const int* __restrict__ sen_len)
{
    extern __shared__ float sm[];
    float* QsT = sm;               // [d][q]  (transposed)
    float* KP  = sm + 64 * 68;     // phase1: KsT [d][k]; phase2: PsT [k][q]
    float* Vs  = sm + 2 * 64 * 68; // [k][d]

    const int bh = blockIdx.y;
    const int b  = bh >> 4;
    const int h  = bh & 15;
    const int q0 = blockIdx.x * 64;
    const float* Qg = g_Qh + (size_t)bh * S_ * HD;
    const float* Kg = g_Kh + (size_t)bh * S_ * HD;
    const float* Vg = g_Vh + (size_t)bh * S_ * HD;
    const int sen    = sen_len[b];
    const int kv_len = min(q0 + 64, sen);

    const int t  = threadIdx.x;
    const int tx = t & 15, ty = t >> 4;

    // Load Q tile transposed (scale already folded in by proj_kernel)
#pragma unroll
    for (int it = 0; it < 4; it++) {
        int idx = t + it * 256;
        int row = idx >> 4, dq = idx & 15;
        float4 v = *(const float4*)&Qg[(size_t)(q0 + row) * HD + dq * 4];
        QsT[(dq * 4 + 0) * 68 + row] = v.x; QsT[(dq * 4 + 1) * 68 + row] = v.y;
        QsT[(dq * 4 + 2) * 68 + row] = v.z; QsT[(dq * 4 + 3) * 68 + row] = v.w;
    }

    float m[4], l[4], o[4][4];
#pragma unroll
    for (int r = 0; r < 4; r++) {
        m[r] = NEG_BIG; l[r] = 0.f;
#pragma unroll
        for (int c = 0; c < 4; c++) o[r][c] = 0.f;
    }

    for (int k0 = 0; k0 < kv_len; k0 += 64) {
        __syncthreads();   // Q visible; previous phase-2 reads of KP/Vs done
#pragma unroll
        for (int it = 0; it < 4; it++) {
            int idx = t + it * 256;
            int row = idx >> 4, dq = idx & 15;
            float4 kv = *(const float4*)&Kg[(size_t)(k0 + row) * HD + dq * 4];
            KP[(dq * 4 + 0) * 68 + row] = kv.x; KP[(dq * 4 + 1) * 68 + row] = kv.y;
            KP[(dq * 4 + 2) * 68 + row] = kv.z; KP[(dq * 4 + 3) * 68 + row] = kv.w;
            float4 vv = *(const float4*)&Vg[(size_t)(k0 + row) * HD + dq * 4];
            *(float4*)&Vs[row * 68 + dq * 4] = vv;
        }
        __syncthreads();

        // S = Q @ K^T (scale pre-folded). rows = queries ty*4+r, cols = keys tx*4+c
        float s[4][4];
#pragma unroll
        for (int r = 0; r < 4; r++)
#pragma unroll
            for (int c = 0; c < 4; c++) s[r][c] = 0.f;
#pragma unroll 8
        for (int dd = 0; dd < 64; dd++) {
            float4 av = *(const float4*)&QsT[dd * 68 + ty * 4];
            float4 bv = *(const float4*)&KP[dd * 68 + tx * 4];
            float aa[4] = {av.x, av.y, av.z, av.w};
            float bb[4] = {bv.x, bv.y, bv.z, bv.w};
#pragma unroll
            for (int r = 0; r < 4; r++)
#pragma unroll
                for (int c = 0; c < 4; c++) s[r][c] += aa[r] * bb[c];
        }

        // causal + padding mask (matches reference -1e9 semantics)
#pragma unroll
        for (int r = 0; r < 4; r++) {
            int i = q0 + ty * 4 + r;
#pragma unroll
            for (int c = 0; c < 4; c++) {
                int j = k0 + tx * 4 + c;
                if (j > i || j >= sen) s[r][c] = NEG_BIG;
            }
        }

        // online softmax update (row stats reduced over the 16 tx lanes)
#pragma unroll
        for (int r = 0; r < 4; r++) {
            float tm = fmaxf(fmaxf(s[r][0], s[r][1]), fmaxf(s[r][2], s[r][3]));
            tm = fmaxf(tm, __shfl_xor_sync(0xffffffffu, tm, 1));
            tm = fmaxf(tm, __shfl_xor_sync(0xffffffffu, tm, 2));
            tm = fmaxf(tm, __shfl_xor_sync(0xffffffffu, tm, 4));
            tm = fmaxf(tm, __shfl_xor_sync(0xffffffffu, tm, 8));
            float mnew  = fmaxf(m[r], tm);
            float alpha = __expf(m[r] - mnew);
            float rsum = 0.f;
#pragma unroll
            for (int c = 0; c < 4; c++) {
                float p = __expf(s[r][c] - mnew);
                s[r][c] = p;
                rsum += p;
            }
            rsum += __shfl_xor_sync(0xffffffffu, rsum, 1);
            rsum += __shfl_xor_sync(0xffffffffu, rsum, 2);
            rsum += __shfl_xor_sync(0xffffffffu, rsum, 4);
            rsum += __shfl_xor_sync(0xffffffffu, rsum, 8);
            l[r] = l[r] * alpha + rsum;
            m[r] = mnew;
#pragma unroll
            for (int c = 0; c < 4; c++) o[r][c] *= alpha;
        }

        __syncthreads();   // all KsT reads done; safe to overwrite with PsT
#pragma unroll
        for (int r = 0; r < 4; r++)
#pragma unroll
            for (int c = 0; c < 4; c++)
                KP[(tx * 4 + c) * 68 + ty * 4 + r] = s[r][c];
        __syncthreads();

        // O += P @ V. rows = queries ty*4+r, cols = head-dim tx*4+c.
        // Masked keys have p == 0 exactly, so summing all 64 is exact.
#pragma unroll 8
        for (int kk = 0; kk < 64; kk++) {
            float4 av = *(const float4*)&KP[kk * 68 + ty * 4];
            float4 bv = *(const float4*)&Vs[kk * 68 + tx * 4];
            float aa[4] = {av.x, av.y, av.z, av.w};
            float bb[4] = {bv.x, bv.y, bv.z, bv.w};
#pragma unroll
            for (int r = 0; r < 4; r++)
#pragma unroll
                for (int c = 0; c < 4; c++) o[r][c] += aa[r] * bb[c];
        }
    }

    // finalize: ctx[b, s, h*64 + j]
#pragma unroll
    for (int r = 0; r < 4; r++) {
        float inv = 1.f / l[r];
        int i = q0 + ty * 4 + r;
        float4 ov = make_float4(o[r][0] * inv, o[r][1] * inv,
                                o[r][2] * inv, o[r][3] * inv);
        *(float4*)&g_ctx[((size_t)b * S_ + i) * D_ + h * HD + tx * 4] = ov;
    }
}

// ---------------------------------------------------------------------------
// Output projection + residual: out = ctx @ Wo^T + q
// ---------------------------------------------------------------------------
__global__ __launch_bounds__(256) void oproj_kernel(
    const float* __restrict__ Wo, const float* __restrict__ resid,
    float* __restrict__ out)
{
    __shared__ float As[16][68];
    __shared__ float Bs[16][68];

    const int m0 = blockIdx.y * 64;
    const int n0 = blockIdx.x * 64;
    const int t  = threadIdx.x;
    const int tx = t & 15, ty = t >> 4;
    const int lr = t >> 2, lq = t & 3;

    float acc[4][4];
#pragma unroll
    for (int r = 0; r < 4; r++)
#pragma unroll
        for (int c = 0; c < 4; c++) acc[r][c] = 0.f;

    const float* Ap = g_ctx + (size_t)(m0 + lr) * D_ + lq * 4;
    const float* Bp = Wo + (size_t)(n0 + lr) * D_ + lq * 4;

    for (int kt = 0; kt < D_; kt += 16) {
        float4 a = *(const float4*)(Ap + kt);
        float4 b = *(const float4*)(Bp + kt);
        __syncthreads();
        As[lq * 4 + 0][lr] = a.x; As[lq * 4 + 1][lr] = a.y;
        As[lq * 4 + 2][lr] = a.z; As[lq * 4 + 3][lr] = a.w;
        Bs[lq * 4 + 0][lr] = b.x; Bs[lq * 4 + 1][lr] = b.y;
        Bs[lq * 4 + 2][lr] = b.z; Bs[lq * 4 + 3][lr] = b.w;
        __syncthreads();
#pragma unroll
        for (int kk = 0; kk < 16; kk++) {
            float4 av = *(const float4*)&As[kk][ty * 4];
            float4 bv = *(const float4*)&Bs[kk][tx * 4];
            float aa[4] = {av.x, av.y, av.z, av.w};
            float bb[4] = {bv.x, bv.y, bv.z, bv.w};
#pragma unroll
            for (int r = 0; r < 4; r++)
#pragma unroll
                for (int c = 0; c < 4; c++) acc[r][c] += aa[r] * bb[c];
        }
    }

#pragma unroll
    for (int r = 0; r < 4; r++) {
        int row = m0 + ty * 4 + r;
        int col = n0 + tx * 4;
        float4 rv = *(const float4*)&resid[(size_t)row * D_ + col];
        float4 ov = make_float4(acc[r][0] + rv.x, acc[r][1] + rv.y,
                                acc[r][2] + rv.z, acc[r][3] + rv.w);
        *(float4*)&out[(size_t)row * D_ + col] = ov;
    }
}

// ---------------------------------------------------------------------------
// LayerNorm (biased variance) in place on out. One block per 1024-elem row.
// ---------------------------------------------------------------------------
__global__ __launch_bounds__(256) void ln_kernel(
    float* __restrict__ out, const float* __restrict__ gamma,
    const float* __restrict__ beta)
{
    __shared__ float sbuf[8], ssbuf[8], red[2];
    const int row = blockIdx.x;
    float* p = out + (size_t)row * D_;
    const int t = threadIdx.x;

    float4 x = *(const float4*)&p[t * 4];
    float s  = x.x + x.y + x.z + x.w;
    float ss = x.x * x.x + x.y * x.y + x.z * x.z + x.w * x.w;
#pragma unroll
    for (int off = 16; off; off >>= 1) {
        s  += __shfl_xor_sync(0xffffffffu, s, off);
        ss += __shfl_xor_sync(0xffffffffu, ss, off);
    }
    if ((t & 31) == 0) { sbuf[t >> 5] = s; ssbuf[t >> 5] = ss; }
    __syncthreads();
    if (t == 0) {
        float S = 0.f, SS = 0.f;
        for (int i = 0; i < 8; i++) { S += sbuf[i]; SS += ssbuf[i]; }
        red[0] = S; red[1] = SS;
    }
    __syncthreads();
    float mean = red[0] * (1.f / 1024.f);
    float var  = red[1] * (1.f / 1024.f) - mean * mean;
    float inv  = rsqrtf(var + 1e-5f);

    float4 g  = *(const float4*)&gamma[t * 4];
    float4 bb = *(const float4*)&beta[t * 4];
    float4 y;
    y.x = (x.x - mean) * inv * g.x + bb.x;
    y.y = (x.y - mean) * inv * g.y + bb.y;
    y.z = (x.z - mean) * inv * g.z + bb.z;
    y.w = (x.w - mean) * inv * g.w + bb.w;
    *(float4*)&p[t * 4] = y;
}

// ---------------------------------------------------------------------------
extern "C" void kernel_launch(void* const* d_in, const int* in_sizes, int n_in,
                              void* d_out, int out_size)
{
    const float* q     = (const float*)d_in[0];
    const float* k     = (const float*)d_in[1];
    const float* v     = (const float*)d_in[2];
    const float* Wq    = (const float*)d_in[3];
    const float* Wk    = (const float*)d_in[4];
    const float* Wv    = (const float*)d_in[5];
    const float* Wo    = (const float*)d_in[6];
    const float* gamma = (const float*)d_in[7];
    const float* beta  = (const float*)d_in[8];
    const int*   sen   = (const int*)d_in[9];
    float* out = (float*)d_out;

    const int ATTN_SMEM = 3 * 64 * 68 * (int)sizeof(float);  // 52224 B > 48K
    cudaFuncSetAttribute(attn_kernel,
                         cudaFuncAttributeMaxDynamicSharedMemorySize, ATTN_SMEM);

    proj_kernel<<<dim3(16, 128, 3), 256>>>(q, k, v, Wq, Wk, Wv);
    attn_kernel<<<dim3(S_ / 64, B_ * H_), 256, ATTN_SMEM>>>(sen);
    oproj_kernel<<<dim3(16, 128), 256>>>(Wo, q, out);
    ln_kernel<<<ROWS, 256>>>(out, gamma, beta);
}

// round 8
// speedup vs baseline: 3.0049x; 3.0049x over previous
#include <cuda_runtime.h>

#define S_   2048
#define D_   1024
#define H_   16
#define B_   4
#define ROWS (B_*S_)
#define LOG2E 1.4426950408889634f

// Scratch (allocation-free): module .bss
__device__ float g_Qh[(size_t)B_*H_*S_*64];
__device__ float g_Kh[(size_t)B_*H_*S_*64];
__device__ float g_Vh[(size_t)B_*H_*S_*64];
__device__ float g_ctx[(size_t)ROWS*D_];

__device__ __forceinline__ unsigned f2tf(float x) {
    unsigned u; asm("cvt.rna.tf32.f32 %0, %1;" : "=r"(u) : "f"(x)); return u;
}
__device__ __forceinline__ float ex2f(float x) {
    float y; asm("ex2.approx.f32 %0, %1;" : "=f"(y) : "f"(x)); return y;
}
__device__ __forceinline__ void mma8(float* c, const unsigned* a, const unsigned* b) {
    asm volatile(
        "mma.sync.aligned.m16n8k8.row.col.f32.tf32.tf32.f32 "
        "{%0,%1,%2,%3},{%4,%5,%6,%7},{%8,%9},{%0,%1,%2,%3};\n"
        : "+f"(c[0]), "+f"(c[1]), "+f"(c[2]), "+f"(c[3])
        : "r"(a[0]), "r"(a[1]), "r"(a[2]), "r"(a[3]), "r"(b[0]), "r"(b[1]));
}

// ---------------------------------------------------------------------------
// QKV projection: O = X @ W^T (NT), tf32 mma. 128x128 tile, BK=16, 8 warps,
// warp tile 64x32. Double-buffered smem (pitch 20 words -> conflict-free
// fragment loads). Epilogue remaps to [b,h,s,64]; Q folds 0.125*log2(e).
// ---------------------------------------------------------------------------
__global__ __launch_bounds__(256) void proj_kernel(
    const float* __restrict__ Xq, const float* __restrict__ Xk, const float* __restrict__ Xv,
    const float* __restrict__ Wq, const float* __restrict__ Wk, const float* __restrict__ Wv)
{
    __shared__ unsigned As[2][128 * 20];
    __shared__ unsigned Bs[2][128 * 20];

    const int z = blockIdx.z;
    const float* X = (z == 0) ? Xq : ((z == 1) ? Xk : Xv);
    const float* W = (z == 0) ? Wq : ((z == 1) ? Wk : Wv);
    float*       O = (z == 0) ? g_Qh : ((z == 1) ? g_Kh : g_Vh);
    const float scale = (z == 0) ? 0.125f * LOG2E : 1.0f;

    const int m0 = blockIdx.y * 128, n0 = blockIdx.x * 128;
    const int t = threadIdx.x;
    const int warp = t >> 5, l = t & 31, g = l >> 2, t4 = l & 3;
    const int wm = (warp >> 2) * 64, wn = (warp & 3) * 32;
    const int lrow = t >> 2, lc4 = (t & 3) * 4;

    const float* Ag = X + (size_t)m0 * D_;
    const float* Bg = W + (size_t)n0 * D_;

    float acc[4][4][4];
#pragma unroll
    for (int mt = 0; mt < 4; mt++)
#pragma unroll
        for (int nt = 0; nt < 4; nt++)
#pragma unroll
            for (int i = 0; i < 4; i++) acc[mt][nt][i] = 0.f;

    // prefetch kt = 0
    {
        float4 a0 = *(const float4*)&Ag[(size_t)lrow * D_ + lc4];
        float4 a1 = *(const float4*)&Ag[(size_t)(lrow + 64) * D_ + lc4];
        float4 b0 = *(const float4*)&Bg[(size_t)lrow * D_ + lc4];
        float4 b1 = *(const float4*)&Bg[(size_t)(lrow + 64) * D_ + lc4];
        unsigned* p = &As[0][lrow * 20 + lc4];
        p[0] = f2tf(a0.x); p[1] = f2tf(a0.y); p[2] = f2tf(a0.z); p[3] = f2tf(a0.w);
        p = &As[0][(lrow + 64) * 20 + lc4];
        p[0] = f2tf(a1.x); p[1] = f2tf(a1.y); p[2] = f2tf(a1.z); p[3] = f2tf(a1.w);
        p = &Bs[0][lrow * 20 + lc4];
        p[0] = f2tf(b0.x); p[1] = f2tf(b0.y); p[2] = f2tf(b0.z); p[3] = f2tf(b0.w);
        p = &Bs[0][(lrow + 64) * 20 + lc4];
        p[0] = f2tf(b1.x); p[1] = f2tf(b1.y); p[2] = f2tf(b1.z); p[3] = f2tf(b1.w);
    }
    __syncthreads();

    for (int kt = 0; kt < 64; kt++) {
        const int cur = kt & 1;
        float4 na0, na1, nb0, nb1;
        if (kt < 63) {
            const int ko = (kt + 1) * 16 + lc4;
            na0 = *(const float4*)&Ag[(size_t)lrow * D_ + ko];
            na1 = *(const float4*)&Ag[(size_t)(lrow + 64) * D_ + ko];
            nb0 = *(const float4*)&Bg[(size_t)lrow * D_ + ko];
            nb1 = *(const float4*)&Bg[(size_t)(lrow + 64) * D_ + ko];
        }
        const unsigned* Ab = As[cur];
        const unsigned* Bb = Bs[cur];
#pragma unroll
        for (int ks = 0; ks < 2; ks++) {
            const int k0 = ks * 8;
            unsigned af[4][4], bf[4][2];
#pragma unroll
            for (int mt = 0; mt < 4; mt++) {
                const int r = (wm + mt * 16 + g) * 20 + k0 + t4;
                af[mt][0] = Ab[r];     af[mt][1] = Ab[r + 8 * 20];
                af[mt][2] = Ab[r + 4]; af[mt][3] = Ab[r + 8 * 20 + 4];
            }
#pragma unroll
            for (int nt = 0; nt < 4; nt++) {
                const int r = (wn + nt * 8 + g) * 20 + k0 + t4;
                bf[nt][0] = Bb[r];     bf[nt][1] = Bb[r + 4];
            }
#pragma unroll
            for (int mt = 0; mt < 4; mt++)
#pragma unroll
                for (int nt = 0; nt < 4; nt++)
                    mma8(acc[mt][nt], af[mt], bf[nt]);
        }
        if (kt < 63) {
            const int nxt = cur ^ 1;
            unsigned* p = &As[nxt][lrow * 20 + lc4];
            p[0] = f2tf(na0.x); p[1] = f2tf(na0.y); p[2] = f2tf(na0.z); p[3] = f2tf(na0.w);
            p = &As[nxt][(lrow + 64) * 20 + lc4];
            p[0] = f2tf(na1.x); p[1] = f2tf(na1.y); p[2] = f2tf(na1.z); p[3] = f2tf(na1.w);
            p = &Bs[nxt][lrow * 20 + lc4];
            p[0] = f2tf(nb0.x); p[1] = f2tf(nb0.y); p[2] = f2tf(nb0.z); p[3] = f2tf(nb0.w);
            p = &Bs[nxt][(lrow + 64) * 20 + lc4];
            p[0] = f2tf(nb1.x); p[1] = f2tf(nb1.y); p[2] = f2tf(nb1.z); p[3] = f2tf(nb1.w);
        }
        __syncthreads();
    }

#pragma unroll
    for (int mt = 0; mt < 4; mt++) {
        const int row = m0 + wm + mt * 16 + g;
        const int bb = row >> 11, s = row & 2047;
#pragma unroll
        for (int nt = 0; nt < 4; nt++) {
            const int col = n0 + wn + nt * 8 + 2 * t4;
            const int h = col >> 6, cl = col & 63;
            *(float2*)&O[(((size_t)bb * H_ + h) * S_ + s) * 64 + cl] =
                make_float2(acc[mt][nt][0] * scale, acc[mt][nt][1] * scale);
            *(float2*)&O[(((size_t)bb * H_ + h) * S_ + (s + 8)) * 64 + cl] =
                make_float2(acc[mt][nt][2] * scale, acc[mt][nt][3] * scale);
        }
    }
}

// ---------------------------------------------------------------------------
// Flash attention, tf32 mma. Block = (b,h, 64-query tile), 4 warps; warp w
// owns 16 query rows, Q fragments live in registers across the KV loop.
// K/P smem pitch 68 (CF a/b fragment loads), V pitch 72 (CF transposed-role
// reads -> PV consumes V in natural [key][d] layout, no transpose pass).
// Softmax in base 2 (log2e folded into Q at projection).
// ---------------------------------------------------------------------------
__global__ __launch_bounds__(128) void attn_kernel(const int* __restrict__ sen_len)
{
    extern __shared__ unsigned smu[];
    unsigned* Ks = smu;                 // [64][68]
    unsigned* Vs = smu + 64 * 68;       // [64][72] natural [key][d]
    unsigned* Ps = smu + 64 * 68 + 64 * 72;  // [64][68]

    const int bh = blockIdx.y;
    const int b = bh >> 4, h = bh & 15;
    const int q0 = blockIdx.x * 64;
    const float* Qg = g_Qh + (size_t)bh * S_ * 64;
    const float* Kg = g_Kh + (size_t)bh * S_ * 64;
    const float* Vg = g_Vh + (size_t)bh * S_ * 64;
    const int sen = sen_len[b];
    const int kv_len = min(q0 + 64, sen);

    const int t = threadIdx.x;
    const int warp = t >> 5, l = t & 31, g = l >> 2, t4 = l & 3;
    const int wq = warp * 16;
    unsigned* Pw = Ps + wq * 68;

    // Q fragments -> registers (scale + log2e already folded in)
    unsigned qa[8][4];
    {
        const float* Qr0 = Qg + (size_t)(q0 + wq + g) * 64;
        const float* Qr1 = Qr0 + 8 * 64;
#pragma unroll
        for (int kt = 0; kt < 8; kt++) {
            qa[kt][0] = f2tf(Qr0[kt * 8 + t4]);
            qa[kt][1] = f2tf(Qr1[kt * 8 + t4]);
            qa[kt][2] = f2tf(Qr0[kt * 8 + t4 + 4]);
            qa[kt][3] = f2tf(Qr1[kt * 8 + t4 + 4]);
        }
    }

    float oacc[8][4];
#pragma unroll
    for (int nt = 0; nt < 8; nt++)
#pragma unroll
        for (int i = 0; i < 4; i++) oacc[nt][i] = 0.f;
    float m0r = -1e30f, m1r = -1e30f, l0r = 0.f, l1r = 0.f;

    const int row0 = q0 + wq + g, row1 = row0 + 8;

    for (int k0 = 0; k0 < kv_len; k0 += 64) {
        __syncthreads();   // previous block's Ks/Vs reads done
#pragma unroll
        for (int it = 0; it < 8; it++) {
            const int f = t + it * 128;
            const int row = f >> 4, c4 = f & 15;
            float4 kv4 = *(const float4*)&Kg[(size_t)(k0 + row) * 64 + c4 * 4];
            *(uint4*)&Ks[row * 68 + c4 * 4] =
                make_uint4(f2tf(kv4.x), f2tf(kv4.y), f2tf(kv4.z), f2tf(kv4.w));
            float4 vv4 = *(const float4*)&Vg[(size_t)(k0 + row) * 64 + c4 * 4];
            *(uint4*)&Vs[row * 72 + c4 * 4] =
                make_uint4(f2tf(vv4.x), f2tf(vv4.y), f2tf(vv4.z), f2tf(vv4.w));
        }
        __syncthreads();

        // S = Q @ K^T
        float sacc[8][4];
#pragma unroll
        for (int nt = 0; nt < 8; nt++)
#pragma unroll
            for (int i = 0; i < 4; i++) sacc[nt][i] = 0.f;
#pragma unroll
        for (int kt = 0; kt < 8; kt++) {
#pragma unroll
            for (int nt = 0; nt < 8; nt++) {
                unsigned bf[2];
                bf[0] = Ks[(nt * 8 + g) * 68 + kt * 8 + t4];
                bf[1] = Ks[(nt * 8 + g) * 68 + kt * 8 + t4 + 4];
                mma8(sacc[nt], qa[kt], bf);
            }
        }

        // causal + padding mask (skip when whole warp tile is unmasked)
        if ((k0 + 63 > q0 + wq) || (k0 + 64 > sen)) {
#pragma unroll
            for (int nt = 0; nt < 8; nt++) {
                const int c = k0 + nt * 8 + 2 * t4;
                if (c > row0     || c >= sen)     sacc[nt][0] = -1e9f;
                if (c + 1 > row0 || c + 1 >= sen) sacc[nt][1] = -1e9f;
                if (c > row1     || c >= sen)     sacc[nt][2] = -1e9f;
                if (c + 1 > row1 || c + 1 >= sen) sacc[nt][3] = -1e9f;
            }
        }

        // online softmax (base-2); row stats live on 4 lanes (t4) per row
        float tm0 = -1e30f, tm1 = -1e30f;
#pragma unroll
        for (int nt = 0; nt < 8; nt++) {
            tm0 = fmaxf(tm0, fmaxf(sacc[nt][0], sacc[nt][1]));
            tm1 = fmaxf(tm1, fmaxf(sacc[nt][2], sacc[nt][3]));
        }
        tm0 = fmaxf(tm0, __shfl_xor_sync(0xffffffffu, tm0, 1));
        tm0 = fmaxf(tm0, __shfl_xor_sync(0xffffffffu, tm0, 2));
        tm1 = fmaxf(tm1, __shfl_xor_sync(0xffffffffu, tm1, 1));
        tm1 = fmaxf(tm1, __shfl_xor_sync(0xffffffffu, tm1, 2));
        const float mn0 = fmaxf(m0r, tm0), mn1 = fmaxf(m1r, tm1);
        const float a0 = ex2f(m0r - mn0), a1 = ex2f(m1r - mn1);
        m0r = mn0; m1r = mn1;
        float s0 = 0.f, s1 = 0.f;
#pragma unroll
        for (int nt = 0; nt < 8; nt++) {
            float p0 = ex2f(sacc[nt][0] - mn0);
            float p1 = ex2f(sacc[nt][1] - mn0);
            float p2 = ex2f(sacc[nt][2] - mn1);
            float p3 = ex2f(sacc[nt][3] - mn1);
            s0 += p0 + p1; s1 += p2 + p3;
            sacc[nt][0] = p0; sacc[nt][1] = p1; sacc[nt][2] = p2; sacc[nt][3] = p3;
            oacc[nt][0] *= a0; oacc[nt][1] *= a0;
            oacc[nt][2] *= a1; oacc[nt][3] *= a1;
        }
        s0 += __shfl_xor_sync(0xffffffffu, s0, 1);
        s0 += __shfl_xor_sync(0xffffffffu, s0, 2);
        s1 += __shfl_xor_sync(0xffffffffu, s1, 1);
        s1 += __shfl_xor_sync(0xffffffffu, s1, 2);
        l0r = l0r * a0 + s0;
        l1r = l1r * a1 + s1;

        // P -> smem (warp-private rows), then O += P @ V
#pragma unroll
        for (int nt = 0; nt < 8; nt++) {
            *(uint2*)&Pw[g * 68 + nt * 8 + 2 * t4] =
                make_uint2(f2tf(sacc[nt][0]), f2tf(sacc[nt][1]));
            *(uint2*)&Pw[(g + 8) * 68 + nt * 8 + 2 * t4] =
                make_uint2(f2tf(sacc[nt][2]), f2tf(sacc[nt][3]));
        }
        __syncwarp();
#pragma unroll
        for (int kt = 0; kt < 8; kt++) {
            unsigned pa[4];
            pa[0] = Pw[g * 68 + kt * 8 + t4];
            pa[1] = Pw[(g + 8) * 68 + kt * 8 + t4];
            pa[2] = Pw[g * 68 + kt * 8 + t4 + 4];
            pa[3] = Pw[(g + 8) * 68 + kt * 8 + t4 + 4];
#pragma unroll
            for (int nt = 0; nt < 8; nt++) {
                unsigned bf[2];
                bf[0] = Vs[(kt * 8 + t4) * 72 + nt * 8 + g];
                bf[1] = Vs[(kt * 8 + t4 + 4) * 72 + nt * 8 + g];
                mma8(oacc[nt], pa, bf);
            }
        }
        __syncwarp();
    }

    // epilogue: ctx[b, s, h*64 + j]
    const float inv0 = 1.f / l0r, inv1 = 1.f / l1r;
#pragma unroll
    for (int nt = 0; nt < 8; nt++) {
        const int cl = h * 64 + nt * 8 + 2 * t4;
        *(float2*)&g_ctx[((size_t)b * S_ + row0) * D_ + cl] =
            make_float2(oacc[nt][0] * inv0, oacc[nt][1] * inv0);
        *(float2*)&g_ctx[((size_t)b * S_ + row1) * D_ + cl] =
            make_float2(oacc[nt][2] * inv1, oacc[nt][3] * inv1);
    }
}

// ---------------------------------------------------------------------------
// Output projection + residual: out = ctx @ Wo^T + resid (same GEMM core)
// ---------------------------------------------------------------------------
__global__ __launch_bounds__(256) void oproj_kernel(
    const float* __restrict__ Wo, const float* __restrict__ resid,
    float* __restrict__ out)
{
    __shared__ unsigned As[2][128 * 20];
    __shared__ unsigned Bs[2][128 * 20];

    const int m0 = blockIdx.y * 128, n0 = blockIdx.x * 128;
    const int t = threadIdx.x;
    const int warp = t >> 5, l = t & 31, g = l >> 2, t4 = l & 3;
    const int wm = (warp >> 2) * 64, wn = (warp & 3) * 32;
    const int lrow = t >> 2, lc4 = (t & 3) * 4;

    const float* Ag = g_ctx + (size_t)m0 * D_;
    const float* Bg = Wo + (size_t)n0 * D_;

    float acc[4][4][4];
#pragma unroll
    for (int mt = 0; mt < 4; mt++)
#pragma unroll
        for (int nt = 0; nt < 4; nt++)
#pragma unroll
            for (int i = 0; i < 4; i++) acc[mt][nt][i] = 0.f;

    {
        float4 a0 = *(const float4*)&Ag[(size_t)lrow * D_ + lc4];
        float4 a1 = *(const float4*)&Ag[(size_t)(lrow + 64) * D_ + lc4];
        float4 b0 = *(const float4*)&Bg[(size_t)lrow * D_ + lc4];
        float4 b1 = *(const float4*)&Bg[(size_t)(lrow + 64) * D_ + lc4];
        unsigned* p = &As[0][lrow * 20 + lc4];
        p[0] = f2tf(a0.x); p[1] = f2tf(a0.y); p[2] = f2tf(a0.z); p[3] = f2tf(a0.w);
        p = &As[0][(lrow + 64) * 20 + lc4];
        p[0] = f2tf(a1.x); p[1] = f2tf(a1.y); p[2] = f2tf(a1.z); p[3] = f2tf(a1.w);
        p = &Bs[0][lrow * 20 + lc4];
        p[0] = f2tf(b0.x); p[1] = f2tf(b0.y); p[2] = f2tf(b0.z); p[3] = f2tf(b0.w);
        p = &Bs[0][(lrow + 64) * 20 + lc4];
        p[0] = f2tf(b1.x); p[1] = f2tf(b1.y); p[2] = f2tf(b1.z); p[3] = f2tf(b1.w);
    }
    __syncthreads();

    for (int kt = 0; kt < 64; kt++) {
        const int cur = kt & 1;
        float4 na0, na1, nb0, nb1;
        if (kt < 63) {
            const int ko = (kt + 1) * 16 + lc4;
            na0 = *(const float4*)&Ag[(size_t)lrow * D_ + ko];
            na1 = *(const float4*)&Ag[(size_t)(lrow + 64) * D_ + ko];
            nb0 = *(const float4*)&Bg[(size_t)lrow * D_ + ko];
            nb1 = *(const float4*)&Bg[(size_t)(lrow + 64) * D_ + ko];
        }
        const unsigned* Ab = As[cur];
        const unsigned* Bb = Bs[cur];
#pragma unroll
        for (int ks = 0; ks < 2; ks++) {
            const int k0 = ks * 8;
            unsigned af[4][4], bf[4][2];
#pragma unroll
            for (int mt = 0; mt < 4; mt++) {
                const int r = (wm + mt * 16 + g) * 20 + k0 + t4;
                af[mt][0] = Ab[r];     af[mt][1] = Ab[r + 8 * 20];
                af[mt][2] = Ab[r + 4]; af[mt][3] = Ab[r + 8 * 20 + 4];
            }
#pragma unroll
            for (int nt = 0; nt < 4; nt++) {
                const int r = (wn + nt * 8 + g) * 20 + k0 + t4;
                bf[nt][0] = Bb[r];     bf[nt][1] = Bb[r + 4];
            }
#pragma unroll
            for (int mt = 0; mt < 4; mt++)
#pragma unroll
                for (int nt = 0; nt < 4; nt++)
                    mma8(acc[mt][nt], af[mt], bf[nt]);
        }
        if (kt < 63) {
            const int nxt = cur ^ 1;
            unsigned* p = &As[nxt][lrow * 20 + lc4];
            p[0] = f2tf(na0.x); p[1] = f2tf(na0.y); p[2] = f2tf(na0.z); p[3] = f2tf(na0.w);
            p = &As[nxt][(lrow + 64) * 20 + lc4];
            p[0] = f2tf(na1.x); p[1] = f2tf(na1.y); p[2] = f2tf(na1.z); p[3] = f2tf(na1.w);
            p = &Bs[nxt][lrow * 20 + lc4];
            p[0] = f2tf(nb0.x); p[1] = f2tf(nb0.y); p[2] = f2tf(nb0.z); p[3] = f2tf(nb0.w);
            p = &Bs[nxt][(lrow + 64) * 20 + lc4];
            p[0] = f2tf(nb1.x); p[1] = f2tf(nb1.y); p[2] = f2tf(nb1.z); p[3] = f2tf(nb1.w);
        }
        __syncthreads();
    }

#pragma unroll
    for (int mt = 0; mt < 4; mt++) {
        const int row = m0 + wm + mt * 16 + g;
#pragma unroll
        for (int nt = 0; nt < 4; nt++) {
            const int col = n0 + wn + nt * 8 + 2 * t4;
            float2 r0 = *(const float2*)&resid[(size_t)row * D_ + col];
            float2 r1 = *(const float2*)&resid[(size_t)(row + 8) * D_ + col];
            *(float2*)&out[(size_t)row * D_ + col] =
                make_float2(acc[mt][nt][0] + r0.x, acc[mt][nt][1] + r0.y);
            *(float2*)&out[(size_t)(row + 8) * D_ + col] =
                make_float2(acc[mt][nt][2] + r1.x, acc[mt][nt][3] + r1.y);
        }
    }
}

// ---------------------------------------------------------------------------
// LayerNorm (biased variance), in place. One block per 1024-elem row.
// ---------------------------------------------------------------------------
__global__ __launch_bounds__(256) void ln_kernel(
    float* __restrict__ out, const float* __restrict__ gamma,
    const float* __restrict__ beta)
{
    __shared__ float sbuf[8], ssbuf[8], red[2];
    const int row = blockIdx.x;
    float* p = out + (size_t)row * D_;
    const int t = threadIdx.x;

    float4 x = *(const float4*)&p[t * 4];
    float s  = x.x + x.y + x.z + x.w;
    float ss = x.x * x.x + x.y * x.y + x.z * x.z + x.w * x.w;
#pragma unroll
    for (int off = 16; off; off >>= 1) {
        s  += __shfl_xor_sync(0xffffffffu, s, off);
        ss += __shfl_xor_sync(0xffffffffu, ss, off);
    }
    if ((t & 31) == 0) { sbuf[t >> 5] = s; ssbuf[t >> 5] = ss; }
    __syncthreads();
    if (t == 0) {
        float S = 0.f, SS = 0.f;
        for (int i = 0; i < 8; i++) { S += sbuf[i]; SS += ssbuf[i]; }
        red[0] = S; red[1] = SS;
    }
    __syncthreads();
    float mean = red[0] * (1.f / 1024.f);
    float var  = red[1] * (1.f / 1024.f) - mean * mean;
    float inv  = rsqrtf(var + 1e-5f);

    float4 gg = *(const float4*)&gamma[t * 4];
    float4 bb = *(const float4*)&beta[t * 4];
    float4 y;
    y.x = (x.x - mean) * inv * gg.x + bb.x;
    y.y = (x.y - mean) * inv * gg.y + bb.y;
    y.z = (x.z - mean) * inv * gg.z + bb.z;
    y.w = (x.w - mean) * inv * gg.w + bb.w;
    *(float4*)&p[t * 4] = y;
}

// ---------------------------------------------------------------------------
extern "C" void kernel_launch(void* const* d_in, const int* in_sizes, int n_in,
                              void* d_out, int out_size)
{
    const float* q     = (const float*)d_in[0];
    const float* k     = (const float*)d_in[1];
    const float* v     = (const float*)d_in[2];
    const float* Wq    = (const float*)d_in[3];
    const float* Wk    = (const float*)d_in[4];
    const float* Wv    = (const float*)d_in[5];
    const float* Wo    = (const float*)d_in[6];
    const float* gamma = (const float*)d_in[7];
    const float* beta  = (const float*)d_in[8];
    const int*   sen   = (const int*)d_in[9];
    float* out = (float*)d_out;

    // attn smem: 64*(68 + 72 + 68) words = 53248 B
    const int ATTN_SMEM = 64 * (68 + 72 + 68) * (int)sizeof(unsigned);
    cudaFuncSetAttribute(attn_kernel,
                         cudaFuncAttributeMaxDynamicSharedMemorySize, ATTN_SMEM);

    proj_kernel<<<dim3(D_ / 128, ROWS / 128, 3), 256>>>(q, k, v, Wq, Wk, Wv);
    attn_kernel<<<dim3(S_ / 64, B_ * H_), 128, ATTN_SMEM>>>(sen);
    oproj_kernel<<<dim3(D_ / 128, ROWS / 128), 256>>>(Wo, q, out);
    ln_kernel<<<ROWS, 256>>>(out, gamma, beta);
}

// round 9
// speedup vs baseline: 5.1974x; 1.7296x over previous
#include <cuda_runtime.h>
#include <cuda_bf16.h>

#define S_   2048
#define D_   1024
#define H_   16
#define B_   4
#define ROWS (B_*S_)
#define NX   (B_*S_*D_)     // 8388608 elems per q/k/v tensor
#define NW   (D_*D_)        // 1048576 elems per weight
#define LOG2E 1.4426950408889634f

// Scratch (allocation-free): module .bss, all bf16
__device__ __nv_bfloat16 g_Xb[(size_t)3*NX];   // q,k,v in bf16
__device__ __nv_bfloat16 g_Wb[(size_t)4*NW];   // Wq,Wk,Wv,Wo in bf16
__device__ __nv_bfloat16 g_Qh[(size_t)B_*H_*S_*64];
__device__ __nv_bfloat16 g_Kh[(size_t)B_*H_*S_*64];
__device__ __nv_bfloat16 g_Vh[(size_t)B_*H_*S_*64];
__device__ __nv_bfloat16 g_ctx[(size_t)ROWS*D_];

__device__ __forceinline__ float ex2f(float x) {
    float y; asm("ex2.approx.f32 %0, %1;" : "=f"(y) : "f"(x)); return y;
}
__device__ __forceinline__ unsigned pk2(float a, float b) {
    __nv_bfloat162 h = __float22bfloat162_rn(make_float2(a, b));
    return *reinterpret_cast<unsigned*>(&h);
}
__device__ __forceinline__ void mma16(float* c, const unsigned* a, const unsigned* b) {
    asm volatile(
        "mma.sync.aligned.m16n8k16.row.col.f32.bf16.bf16.f32 "
        "{%0,%1,%2,%3},{%4,%5,%6,%7},{%8,%9},{%0,%1,%2,%3};\n"
        : "+f"(c[0]), "+f"(c[1]), "+f"(c[2]), "+f"(c[3])
        : "r"(a[0]), "r"(a[1]), "r"(a[2]), "r"(a[3]), "r"(b[0]), "r"(b[1]));
}

// ---------------------------------------------------------------------------
// fp32 -> bf16 conversion pre-pass: q,k,v -> g_Xb; Wq,Wk,Wv,Wo -> g_Wb
// ---------------------------------------------------------------------------
__global__ __launch_bounds__(256) void conv_kernel(
    const float* __restrict__ q, const float* __restrict__ k, const float* __restrict__ v,
    const float* __restrict__ wq, const float* __restrict__ wk,
    const float* __restrict__ wv, const float* __restrict__ wo)
{
    size_t e = ((size_t)blockIdx.x * 256 + threadIdx.x) * 4;
    const float* src;
    __nv_bfloat16* dst;
    if (e < (size_t)3 * NX) {
        int s = (int)(e / NX);
        src = (s == 0) ? q : ((s == 1) ? k : v);
        dst = g_Xb + (size_t)s * NX;
        e -= (size_t)s * NX;
    } else {
        size_t r = e - (size_t)3 * NX;
        int s = (int)(r / NW);
        src = (s == 0) ? wq : ((s == 1) ? wk : ((s == 2) ? wv : wo));
        dst = g_Wb + (size_t)s * NW;
        e = r - (size_t)s * NW;
    }
    float4 x = *(const float4*)(src + e);
    *(__nv_bfloat162*)(dst + e)     = __float22bfloat162_rn(make_float2(x.x, x.y));
    *(__nv_bfloat162*)(dst + e + 2) = __float22bfloat162_rn(make_float2(x.z, x.w));
}

// ---------------------------------------------------------------------------
// QKV projection: O = X @ W^T (NT), bf16 m16n8k16. 128x128 tile, BK=32,
// 8 warps, warp tile 64x32. Smem pitch 20 words (conflict-free fragments).
// Epilogue remaps to [b,h,s,64] bf16; Q folds 0.125*log2(e).
// ---------------------------------------------------------------------------
__global__ __launch_bounds__(256) void proj_kernel()
{
    __shared__ unsigned As[2][128 * 20];
    __shared__ unsigned Bs[2][128 * 20];

    const int z = blockIdx.z;
    const __nv_bfloat16* X = g_Xb + (size_t)z * NX;
    const __nv_bfloat16* W = g_Wb + (size_t)z * NW;
    __nv_bfloat16* O = (z == 0) ? g_Qh : ((z == 1) ? g_Kh : g_Vh);
    const float scale = (z == 0) ? 0.125f * LOG2E : 1.0f;

    const int m0 = blockIdx.y * 128, n0 = blockIdx.x * 128;
    const int t = threadIdx.x;
    const int warp = t >> 5, l = t & 31, g = l >> 2, t4 = l & 3;
    const int wm = (warp >> 2) * 64, wn = (warp & 3) * 32;
    const int lr = t >> 2, lq = (t & 3) * 4;    // loader row, word-quad col

    const __nv_bfloat16* Ag = X + (size_t)(m0 + lr) * D_ + (t & 3) * 8;
    const __nv_bfloat16* Bg = W + (size_t)(n0 + lr) * D_ + (t & 3) * 8;

    float acc[4][4][4];
#pragma unroll
    for (int mt = 0; mt < 4; mt++)
#pragma unroll
        for (int nt = 0; nt < 4; nt++)
#pragma unroll
            for (int i = 0; i < 4; i++) acc[mt][nt][i] = 0.f;

    // prefetch kt=0
    uint4 pa0 = *(const uint4*)Ag;
    uint4 pa1 = *(const uint4*)(Ag + (size_t)64 * D_);
    uint4 pb0 = *(const uint4*)Bg;
    uint4 pb1 = *(const uint4*)(Bg + (size_t)64 * D_);
    *(uint4*)&As[0][lr * 20 + lq] = pa0;
    *(uint4*)&As[0][(lr + 64) * 20 + lq] = pa1;
    *(uint4*)&Bs[0][lr * 20 + lq] = pb0;
    *(uint4*)&Bs[0][(lr + 64) * 20 + lq] = pb1;
    __syncthreads();

    for (int kt = 0; kt < 32; kt++) {
        const int cur = kt & 1;
        if (kt < 31) {
            const int ko = (kt + 1) * 32;
            pa0 = *(const uint4*)(Ag + ko);
            pa1 = *(const uint4*)(Ag + (size_t)64 * D_ + ko);
            pb0 = *(const uint4*)(Bg + ko);
            pb1 = *(const uint4*)(Bg + (size_t)64 * D_ + ko);
        }
        const unsigned* Ab = As[cur];
        const unsigned* Bb = Bs[cur];
#pragma unroll
        for (int ks = 0; ks < 2; ks++) {
            const int kw = ks * 8;
            unsigned af[4][4], bf[4][2];
#pragma unroll
            for (int mt = 0; mt < 4; mt++) {
                const int r = (wm + mt * 16 + g) * 20 + kw + t4;
                af[mt][0] = Ab[r];     af[mt][1] = Ab[r + 8 * 20];
                af[mt][2] = Ab[r + 4]; af[mt][3] = Ab[r + 8 * 20 + 4];
            }
#pragma unroll
            for (int nt = 0; nt < 4; nt++) {
                const int r = (wn + nt * 8 + g) * 20 + kw + t4;
                bf[nt][0] = Bb[r];     bf[nt][1] = Bb[r + 4];
            }
#pragma unroll
            for (int mt = 0; mt < 4; mt++)
#pragma unroll
                for (int nt = 0; nt < 4; nt++)
                    mma16(acc[mt][nt], af[mt], bf[nt]);
        }
        if (kt < 31) {
            const int nxt = cur ^ 1;
            *(uint4*)&As[nxt][lr * 20 + lq] = pa0;
            *(uint4*)&As[nxt][(lr + 64) * 20 + lq] = pa1;
            *(uint4*)&Bs[nxt][lr * 20 + lq] = pb0;
            *(uint4*)&Bs[nxt][(lr + 64) * 20 + lq] = pb1;
        }
        __syncthreads();
    }

#pragma unroll
    for (int mt = 0; mt < 4; mt++) {
        const int row = m0 + wm + mt * 16 + g;
        const int bb = row >> 11, s = row & 2047;
#pragma unroll
        for (int nt = 0; nt < 4; nt++) {
            const int col = n0 + wn + nt * 8 + 2 * t4;
            const int h = col >> 6, cl = col & 63;
            *(unsigned*)&O[(((size_t)bb * H_ + h) * S_ + s) * 64 + cl] =
                pk2(acc[mt][nt][0] * scale, acc[mt][nt][1] * scale);
            *(unsigned*)&O[(((size_t)bb * H_ + h) * S_ + (s + 8)) * 64 + cl] =
                pk2(acc[mt][nt][2] * scale, acc[mt][nt][3] * scale);
        }
    }
}

// ---------------------------------------------------------------------------
// Flash attention, bf16 m16n8k16. Block = (b,h, 64-query tile), 4 warps;
// warp owns 16 query rows; Q fragments in registers for the whole KV loop.
// K staged natural [key][d], V staged TRANSPOSED [d][key], both pitch 36
// (all fragment LDS conflict-free). Softmax output packs directly into PV
// A-fragments (C-layout == A-pair layout) -> no P smem round-trip.
// ---------------------------------------------------------------------------
__global__ __launch_bounds__(128) void attn_kernel(const int* __restrict__ sen_len)
{
    __shared__ unsigned Ks[64 * 36];    // [key][d-pairs]
    __shared__ unsigned VsT[64 * 36];   // [d][key-pairs]

    const int bh = blockIdx.y;
    const int b = bh >> 4, h = bh & 15;
    const int q0 = blockIdx.x * 64;
    const __nv_bfloat16* Qg = g_Qh + (size_t)bh * S_ * 64;
    const __nv_bfloat16* Kg = g_Kh + (size_t)bh * S_ * 64;
    const __nv_bfloat16* Vg = g_Vh + (size_t)bh * S_ * 64;
    const int sen = sen_len[b];
    const int kv_len = min(q0 + 64, sen);

    const int t = threadIdx.x;
    const int warp = t >> 5, l = t & 31, g = l >> 2, t4 = l & 3;
    const int wq = warp * 16;
    const int row0 = q0 + wq + g, row1 = row0 + 8;

    // Q fragments -> registers (scale + log2e folded in at projection)
    unsigned qa[4][4];
    {
        const __nv_bfloat16* Qr0 = Qg + (size_t)row0 * 64;
        const __nv_bfloat16* Qr1 = Qg + (size_t)row1 * 64;
#pragma unroll
        for (int kt = 0; kt < 4; kt++) {
            qa[kt][0] = *(const unsigned*)&Qr0[16 * kt + 2 * t4];
            qa[kt][1] = *(const unsigned*)&Qr1[16 * kt + 2 * t4];
            qa[kt][2] = *(const unsigned*)&Qr0[16 * kt + 8 + 2 * t4];
            qa[kt][3] = *(const unsigned*)&Qr1[16 * kt + 8 + 2 * t4];
        }
    }

    float oacc[8][4];
#pragma unroll
    for (int nt = 0; nt < 8; nt++)
#pragma unroll
        for (int i = 0; i < 4; i++) oacc[nt][i] = 0.f;
    float m0r = -1e30f, m1r = -1e30f, l0r = 0.f, l1r = 0.f;

    const int kp = t & 31, db0 = t >> 5;   // V-transpose: key-pair, d-block

    for (int k0 = 0; k0 < kv_len; k0 += 64) {
        __syncthreads();   // previous iteration's smem reads done
        // K: straight copy (8 lanes per row -> CF stores)
#pragma unroll
        for (int it = 0; it < 4; it++) {
            const int f = t + it * 128;
            const int row = f >> 3, qd = f & 7;
            *(uint4*)&Ks[row * 36 + qd * 4] =
                *(const uint4*)&Kg[(size_t)(k0 + row) * 64 + qd * 8];
        }
        // V: transpose during staging -> VsT[d][key-pair]
#pragma unroll
        for (int it = 0; it < 2; it++) {
            const int db = db0 + it * 4;
            union { uint4 u; unsigned short s[8]; } r0, r1;
            r0.u = *(const uint4*)&Vg[(size_t)(k0 + 2 * kp) * 64 + db * 8];
            r1.u = *(const uint4*)&Vg[(size_t)(k0 + 2 * kp + 1) * 64 + db * 8];
#pragma unroll
            for (int j = 0; j < 8; j++)
                VsT[(db * 8 + j) * 36 + kp] =
                    (unsigned)r0.s[j] | ((unsigned)r1.s[j] << 16);
        }
        __syncthreads();

        // S = Q @ K^T
        float sacc[8][4];
#pragma unroll
        for (int nt = 0; nt < 8; nt++)
#pragma unroll
            for (int i = 0; i < 4; i++) sacc[nt][i] = 0.f;
#pragma unroll
        for (int kt = 0; kt < 4; kt++)
#pragma unroll
            for (int nt = 0; nt < 8; nt++) {
                unsigned bf[2];
                bf[0] = Ks[(nt * 8 + g) * 36 + kt * 8 + t4];
                bf[1] = Ks[(nt * 8 + g) * 36 + kt * 8 + t4 + 4];
                mma16(sacc[nt], qa[kt], bf);
            }

        // causal + padding mask (skip when whole warp tile is unmasked)
        if ((k0 + 63 > row0 - g) || (k0 + 64 > sen)) {
#pragma unroll
            for (int nt = 0; nt < 8; nt++) {
                const int c = k0 + nt * 8 + 2 * t4;
                if (c > row0     || c >= sen)     sacc[nt][0] = -1e9f;
                if (c + 1 > row0 || c + 1 >= sen) sacc[nt][1] = -1e9f;
                if (c > row1     || c >= sen)     sacc[nt][2] = -1e9f;
                if (c + 1 > row1 || c + 1 >= sen) sacc[nt][3] = -1e9f;
            }
        }

        // online softmax (base-2); row stats reduced over the 4 t4 lanes
        float tm0 = -1e30f, tm1 = -1e30f;
#pragma unroll
        for (int nt = 0; nt < 8; nt++) {
            tm0 = fmaxf(tm0, fmaxf(sacc[nt][0], sacc[nt][1]));
            tm1 = fmaxf(tm1, fmaxf(sacc[nt][2], sacc[nt][3]));
        }
        tm0 = fmaxf(tm0, __shfl_xor_sync(0xffffffffu, tm0, 1));
        tm0 = fmaxf(tm0, __shfl_xor_sync(0xffffffffu, tm0, 2));
        tm1 = fmaxf(tm1, __shfl_xor_sync(0xffffffffu, tm1, 1));
        tm1 = fmaxf(tm1, __shfl_xor_sync(0xffffffffu, tm1, 2));
        const float mn0 = fmaxf(m0r, tm0), mn1 = fmaxf(m1r, tm1);
        const float a0 = ex2f(m0r - mn0), a1 = ex2f(m1r - mn1);
        m0r = mn0; m1r = mn1;
        float s0 = 0.f, s1 = 0.f;
#pragma unroll
        for (int nt = 0; nt < 8; nt++) {
            float p0 = ex2f(sacc[nt][0] - mn0);
            float p1 = ex2f(sacc[nt][1] - mn0);
            float p2 = ex2f(sacc[nt][2] - mn1);
            float p3 = ex2f(sacc[nt][3] - mn1);
            s0 += p0 + p1; s1 += p2 + p3;
            sacc[nt][0] = p0; sacc[nt][1] = p1; sacc[nt][2] = p2; sacc[nt][3] = p3;
            oacc[nt][0] *= a0; oacc[nt][1] *= a0;
            oacc[nt][2] *= a1; oacc[nt][3] *= a1;
        }
        s0 += __shfl_xor_sync(0xffffffffu, s0, 1);
        s0 += __shfl_xor_sync(0xffffffffu, s0, 2);
        s1 += __shfl_xor_sync(0xffffffffu, s1, 1);
        s1 += __shfl_xor_sync(0xffffffffu, s1, 2);
        l0r = l0r * a0 + s0;
        l1r = l1r * a1 + s1;

        // O += P @ V : P packs straight from sacc into A-fragments
#pragma unroll
        for (int kt = 0; kt < 4; kt++) {
            unsigned pa[4];
            pa[0] = pk2(sacc[2 * kt][0],     sacc[2 * kt][1]);
            pa[1] = pk2(sacc[2 * kt][2],     sacc[2 * kt][3]);
            pa[2] = pk2(sacc[2 * kt + 1][0], sacc[2 * kt + 1][1]);
            pa[3] = pk2(sacc[2 * kt + 1][2], sacc[2 * kt + 1][3]);
#pragma unroll
            for (int nt = 0; nt < 8; nt++) {
                unsigned bf[2];
                bf[0] = VsT[(nt * 8 + g) * 36 + kt * 8 + t4];
                bf[1] = VsT[(nt * 8 + g) * 36 + kt * 8 + t4 + 4];
                mma16(oacc[nt], pa, bf);
            }
        }
    }

    // epilogue: ctx[b, s, h*64 + j] in bf16
    const float inv0 = 1.f / l0r, inv1 = 1.f / l1r;
#pragma unroll
    for (int nt = 0; nt < 8; nt++) {
        const int cl = h * 64 + nt * 8 + 2 * t4;
        *(unsigned*)&g_ctx[((size_t)b * S_ + row0) * D_ + cl] =
            pk2(oacc[nt][0] * inv0, oacc[nt][1] * inv0);
        *(unsigned*)&g_ctx[((size_t)b * S_ + row1) * D_ + cl] =
            pk2(oacc[nt][2] * inv1, oacc[nt][3] * inv1);
    }
}

// ---------------------------------------------------------------------------
// Output projection + residual: out = ctx @ Wo^T + resid (bf16 GEMM core,
// fp32 residual + output)
// ---------------------------------------------------------------------------
__global__ __launch_bounds__(256) void oproj_kernel(
    const float* __restrict__ resid, float* __restrict__ out)
{
    __shared__ unsigned As[2][128 * 20];
    __shared__ unsigned Bs[2][128 * 20];

    const int m0 = blockIdx.y * 128, n0 = blockIdx.x * 128;
    const int t = threadIdx.x;
    const int warp = t >> 5, l = t & 31, g = l >> 2, t4 = l & 3;
    const int wm = (warp >> 2) * 64, wn = (warp & 3) * 32;
    const int lr = t >> 2, lq = (t & 3) * 4;

    const __nv_bfloat16* Ag = g_ctx + (size_t)(m0 + lr) * D_ + (t & 3) * 8;
    const __nv_bfloat16* Bg = g_Wb + (size_t)3 * NW + (size_t)(n0 + lr) * D_ + (t & 3) * 8;

    float acc[4][4][4];
#pragma unroll
    for (int mt = 0; mt < 4; mt++)
#pragma unroll
        for (int nt = 0; nt < 4; nt++)
#pragma unroll
            for (int i = 0; i < 4; i++) acc[mt][nt][i] = 0.f;

    uint4 pa0 = *(const uint4*)Ag;
    uint4 pa1 = *(const uint4*)(Ag + (size_t)64 * D_);
    uint4 pb0 = *(const uint4*)Bg;
    uint4 pb1 = *(const uint4*)(Bg + (size_t)64 * D_);
    *(uint4*)&As[0][lr * 20 + lq] = pa0;
    *(uint4*)&As[0][(lr + 64) * 20 + lq] = pa1;
    *(uint4*)&Bs[0][lr * 20 + lq] = pb0;
    *(uint4*)&Bs[0][(lr + 64) * 20 + lq] = pb1;
    __syncthreads();

    for (int kt = 0; kt < 32; kt++) {
        const int cur = kt & 1;
        if (kt < 31) {
            const int ko = (kt + 1) * 32;
            pa0 = *(const uint4*)(Ag + ko);
            pa1 = *(const uint4*)(Ag + (size_t)64 * D_ + ko);
            pb0 = *(const uint4*)(Bg + ko);
            pb1 = *(const uint4*)(Bg + (size_t)64 * D_ + ko);
        }
        const unsigned* Ab = As[cur];
        const unsigned* Bb = Bs[cur];
#pragma unroll
        for (int ks = 0; ks < 2; ks++) {
            const int kw = ks * 8;
            unsigned af[4][4], bf[4][2];
#pragma unroll
            for (int mt = 0; mt < 4; mt++) {
                const int r = (wm + mt * 16 + g) * 20 + kw + t4;
                af[mt][0] = Ab[r];     af[mt][1] = Ab[r + 8 * 20];
                af[mt][2] = Ab[r + 4]; af[mt][3] = Ab[r + 8 * 20 + 4];
            }
#pragma unroll
            for (int nt = 0; nt < 4; nt++) {
                const int r = (wn + nt * 8 + g) * 20 + kw + t4;
                bf[nt][0] = Bb[r];     bf[nt][1] = Bb[r + 4];
            }
#pragma unroll
            for (int mt = 0; mt < 4; mt++)
#pragma unroll
                for (int nt = 0; nt < 4; nt++)
                    mma16(acc[mt][nt], af[mt], bf[nt]);
        }
        if (kt < 31) {
            const int nxt = cur ^ 1;
            *(uint4*)&As[nxt][lr * 20 + lq] = pa0;
            *(uint4*)&As[nxt][(lr + 64) * 20 + lq] = pa1;
            *(uint4*)&Bs[nxt][lr * 20 + lq] = pb0;
            *(uint4*)&Bs[nxt][(lr + 64) * 20 + lq] = pb1;
        }
        __syncthreads();
    }

#pragma unroll
    for (int mt = 0; mt < 4; mt++) {
        const int row = m0 + wm + mt * 16 + g;
#pragma unroll
        for (int nt = 0; nt < 4; nt++) {
            const int col = n0 + wn + nt * 8 + 2 * t4;
            float2 r0 = *(const float2*)&resid[(size_t)row * D_ + col];
            float2 r1 = *(const float2*)&resid[(size_t)(row + 8) * D_ + col];
            *(float2*)&out[(size_t)row * D_ + col] =
                make_float2(acc[mt][nt][0] + r0.x, acc[mt][nt][1] + r0.y);
            *(float2*)&out[(size_t)(row + 8) * D_ + col] =
                make_float2(acc[mt][nt][2] + r1.x, acc[mt][nt][3] + r1.y);
        }
    }
}

// ---------------------------------------------------------------------------
// LayerNorm (biased variance), in place. One block per 1024-elem row.
// ---------------------------------------------------------------------------
__global__ __launch_bounds__(256) void ln_kernel(
    float* __restrict__ out, const float* __restrict__ gamma,
    const float* __restrict__ beta)
{
    __shared__ float sbuf[8], ssbuf[8], red[2];
    const int row = blockIdx.x;
    float* p = out + (size_t)row * D_;
    const int t = threadIdx.x;

    float4 x = *(const float4*)&p[t * 4];
    float s  = x.x + x.y + x.z + x.w;
    float ss = x.x * x.x + x.y * x.y + x.z * x.z + x.w * x.w;
#pragma unroll
    for (int off = 16; off; off >>= 1) {
        s  += __shfl_xor_sync(0xffffffffu, s, off);
        ss += __shfl_xor_sync(0xffffffffu, ss, off);
    }
    if ((t & 31) == 0) { sbuf[t >> 5] = s; ssbuf[t >> 5] = ss; }
    __syncthreads();
    if (t == 0) {
        float S = 0.f, SS = 0.f;
        for (int i = 0; i < 8; i++) { S += sbuf[i]; SS += ssbuf[i]; }
        red[0] = S; red[1] = SS;
    }
    __syncthreads();
    float mean = red[0] * (1.f / 1024.f);
    float var  = red[1] * (1.f / 1024.f) - mean * mean;
    float inv  = rsqrtf(var + 1e-5f);

    float4 gg = *(const float4*)&gamma[t * 4];
    float4 bb = *(const float4*)&beta[t * 4];
    float4 y;
    y.x = (x.x - mean) * inv * gg.x + bb.x;
    y.y = (x.y - mean) * inv * gg.y + bb.y;
    y.z = (x.z - mean) * inv * gg.z + bb.z;
    y.w = (x.w - mean) * inv * gg.w + bb.w;
    *(float4*)&p[t * 4] = y;
}

// ---------------------------------------------------------------------------
extern "C" void kernel_launch(void* const* d_in, const int* in_sizes, int n_in,
                              void* d_out, int out_size)
{
    const float* q     = (const float*)d_in[0];
    const float* k     = (const float*)d_in[1];
    const float* v     = (const float*)d_in[2];
    const float* Wq    = (const float*)d_in[3];
    const float* Wk    = (const float*)d_in[4];
    const float* Wv    = (const float*)d_in[5];
    const float* Wo    = (const float*)d_in[6];
    const float* gamma = (const float*)d_in[7];
    const float* beta  = (const float*)d_in[8];
    const int*   sen   = (const int*)d_in[9];
    float* out = (float*)d_out;

    conv_kernel<<<(3 * NX + 4 * NW) / (4 * 256), 256>>>(q, k, v, Wq, Wk, Wv, Wo);
    proj_kernel<<<dim3(D_ / 128, ROWS / 128, 3), 256>>>();
    attn_kernel<<<dim3(S_ / 64, B_ * H_), 128>>>(sen);
    oproj_kernel<<<dim3(D_ / 128, ROWS / 128), 256>>>(q, out);
    ln_kernel<<<ROWS, 256>>>(out, gamma, beta);
}

// round 10
// speedup vs baseline: 5.6882x; 1.0944x over previous
#include <cuda_runtime.h>
#include <cuda_bf16.h>

#define S_   2048
#define D_   1024
#define H_   16
#define B_   4
#define ROWS (B_*S_)
#define NX   (B_*S_*D_)     // 8388608 elems per q/k/v tensor
#define NW   (D_*D_)        // 1048576 elems per weight
#define LOG2E 1.4426950408889634f

// Scratch (allocation-free): module .bss, all bf16
__device__ __nv_bfloat16 g_Xb[(size_t)3*NX];   // q,k,v in bf16
__device__ __nv_bfloat16 g_Wb[(size_t)4*NW];   // Wq,Wk,Wv,Wo in bf16
__device__ __nv_bfloat16 g_Qh[(size_t)B_*H_*S_*64];
__device__ __nv_bfloat16 g_Kh[(size_t)B_*H_*S_*64];
__device__ __nv_bfloat16 g_Vh[(size_t)B_*H_*S_*64];
__device__ __nv_bfloat16 g_ctx[(size_t)ROWS*D_];

__device__ __forceinline__ float ex2f(float x) {
    float y; asm("ex2.approx.f32 %0, %1;" : "=f"(y) : "f"(x)); return y;
}
__device__ __forceinline__ unsigned pk2(float a, float b) {
    __nv_bfloat162 h = __float22bfloat162_rn(make_float2(a, b));
    return *reinterpret_cast<unsigned*>(&h);
}
__device__ __forceinline__ void mma16(float* c, const unsigned* a, const unsigned* b) {
    asm volatile(
        "mma.sync.aligned.m16n8k16.row.col.f32.bf16.bf16.f32 "
        "{%0,%1,%2,%3},{%4,%5,%6,%7},{%8,%9},{%0,%1,%2,%3};\n"
        : "+f"(c[0]), "+f"(c[1]), "+f"(c[2]), "+f"(c[3])
        : "r"(a[0]), "r"(a[1]), "r"(a[2]), "r"(a[3]), "r"(b[0]), "r"(b[1]));
}
__device__ __forceinline__ void ldsm4(unsigned* r, unsigned addr) {
    asm volatile("ldmatrix.sync.aligned.m8n8.x4.shared.b16 {%0,%1,%2,%3}, [%4];\n"
        : "=r"(r[0]), "=r"(r[1]), "=r"(r[2]), "=r"(r[3]) : "r"(addr));
}
__device__ __forceinline__ void cpa16(unsigned saddr, const void* g) {
    asm volatile("cp.async.cg.shared.global [%0], [%1], 16;\n"
        :: "r"(saddr), "l"(g));
}

// ---------------------------------------------------------------------------
// fp32 -> bf16 conversion pre-pass: q,k,v -> g_Xb; Wq,Wk,Wv,Wo -> g_Wb
// ---------------------------------------------------------------------------
__global__ __launch_bounds__(256) void conv_kernel(
    const float* __restrict__ q, const float* __restrict__ k, const float* __restrict__ v,
    const float* __restrict__ wq, const float* __restrict__ wk,
    const float* __restrict__ wv, const float* __restrict__ wo)
{
    size_t e = ((size_t)blockIdx.x * 256 + threadIdx.x) * 4;
    const float* src;
    __nv_bfloat16* dst;
    if (e < (size_t)3 * NX) {
        int s = (int)(e / NX);
        src = (s == 0) ? q : ((s == 1) ? k : v);
        dst = g_Xb + (size_t)s * NX;
        e -= (size_t)s * NX;
    } else {
        size_t r = e - (size_t)3 * NX;
        int s = (int)(r / NW);
        src = (s == 0) ? wq : ((s == 1) ? wk : ((s == 2) ? wv : wo));
        dst = g_Wb + (size_t)s * NW;
        e = r - (size_t)s * NW;
    }
    float4 x = *(const float4*)(src + e);
    *(__nv_bfloat162*)(dst + e)     = __float22bfloat162_rn(make_float2(x.x, x.y));
    *(__nv_bfloat162*)(dst + e + 2) = __float22bfloat162_rn(make_float2(x.z, x.w));
}

// ---------------------------------------------------------------------------
// Shared GEMM mainloop: C[128x128] = A[128xD] @ B[128xD]^T (NT), bf16 mma.
// 3-stage cp.async pipeline; pitch-20-word smem rows (ldmatrix phases CF:
// 20r mod 32 spans 8 disjoint 4-word groups); ldmatrix.x4 fragment loads.
// 8 warps, 64x32 warp tiles, BK=32.
// Stage layout: [A 128*20 | B 128*20] words, stride 5120 words = 20480 B.
// ---------------------------------------------------------------------------
#define GEMM_SMEM (3 * 5120 * 4)

__device__ __forceinline__ void gemm_mainloop(
    const __nv_bfloat16* __restrict__ Ablk,   // + m0*D_
    const __nv_bfloat16* __restrict__ Bblk,   // + n0*D_
    float acc[4][4][4])
{
    extern __shared__ unsigned smem_u[];
    const unsigned sbase = (unsigned)__cvta_generic_to_shared(smem_u);
    const int t = threadIdx.x;
    const int warp = t >> 5, l = t & 31;
    const int wm = (warp >> 2) * 64, wn = (warp & 3) * 32;

    // loaders: thread t -> row t>>2 (and +64), 16B chunk t&3
    const int lrow = t >> 2, lch = t & 3;
    const __nv_bfloat16* gA0 = Ablk + (size_t)lrow * D_ + lch * 8;
    const __nv_bfloat16* gA1 = gA0 + (size_t)64 * D_;
    const __nv_bfloat16* gB0 = Bblk + (size_t)lrow * D_ + lch * 8;
    const __nv_bfloat16* gB1 = gB0 + (size_t)64 * D_;
    const unsigned sA0 = sbase + (lrow * 20 + lch * 4) * 4;
    const unsigned sA1 = sA0 + 64 * 80;
    const unsigned sB0 = sA0 + 2560 * 4;
    const unsigned sB1 = sB0 + 64 * 80;

    // ldmatrix lane addressing (word offsets within a stage)
    const int arow = (l & 7) + 8 * ((l >> 3) & 1);   // A: m8-pair select
    const int acw  = 4 * (l >> 4);                   // A: k16-half select
    const int brow = (l & 7) + 8 * (l >> 4);         // B: n8-pair select
    const int bcw  = 4 * ((l >> 3) & 1);             // B: k16-half select

#pragma unroll
    for (int mt = 0; mt < 4; mt++)
#pragma unroll
        for (int nt = 0; nt < 4; nt++)
#pragma unroll
            for (int i = 0; i < 4; i++) acc[mt][nt][i] = 0.f;

    // prefetch stages 0, 1
#pragma unroll
    for (int s = 0; s < 2; s++) {
        const int ko = s * 32;
        const unsigned so = s * 20480;
        cpa16(sA0 + so, gA0 + ko); cpa16(sA1 + so, gA1 + ko);
        cpa16(sB0 + so, gB0 + ko); cpa16(sB1 + so, gB1 + ko);
        asm volatile("cp.async.commit_group;\n" ::: "memory");
    }

    for (int kt = 0; kt < 32; kt++) {
        if (kt < 31) asm volatile("cp.async.wait_group 1;\n" ::: "memory");
        else         asm volatile("cp.async.wait_group 0;\n" ::: "memory");
        __syncthreads();
        if (kt + 2 < 32) {
            const int ko = (kt + 2) * 32;
            const unsigned so = ((kt + 2) % 3) * 20480;
            cpa16(sA0 + so, gA0 + ko); cpa16(sA1 + so, gA1 + ko);
            cpa16(sB0 + so, gB0 + ko); cpa16(sB1 + so, gB1 + ko);
            asm volatile("cp.async.commit_group;\n" ::: "memory");
        }
        const unsigned stA = sbase + (kt % 3) * 20480;
        const unsigned stB = stA + 2560 * 4;
#pragma unroll
        for (int ks = 0; ks < 2; ks++) {
            unsigned af[4][4], bq[2][4];
#pragma unroll
            for (int mt = 0; mt < 4; mt++)
                ldsm4(af[mt], stA + ((wm + mt * 16 + arow) * 20 + ks * 8 + acw) * 4);
#pragma unroll
            for (int p = 0; p < 2; p++)
                ldsm4(bq[p], stB + ((wn + p * 16 + brow) * 20 + ks * 8 + bcw) * 4);
#pragma unroll
            for (int mt = 0; mt < 4; mt++)
#pragma unroll
                for (int nt = 0; nt < 4; nt++) {
                    unsigned bfr[2] = { bq[nt >> 1][(nt & 1) * 2],
                                        bq[nt >> 1][(nt & 1) * 2 + 1] };
                    mma16(acc[mt][nt], af[mt], bfr);
                }
        }
        // next iteration's wait+sync protects the buffer being overwritten
    }
}

// ---------------------------------------------------------------------------
// QKV projection: O = X @ W^T; epilogue remaps to [b,h,s,64] bf16,
// Q folds 0.125*log2(e).
// ---------------------------------------------------------------------------
__global__ __launch_bounds__(256) void proj_kernel()
{
    const int z = blockIdx.z;
    const __nv_bfloat16* X = g_Xb + (size_t)z * NX;
    const __nv_bfloat16* W = g_Wb + (size_t)z * NW;
    __nv_bfloat16* O = (z == 0) ? g_Qh : ((z == 1) ? g_Kh : g_Vh);
    const float scale = (z == 0) ? 0.125f * LOG2E : 1.0f;

    const int m0 = blockIdx.y * 128, n0 = blockIdx.x * 128;
    float acc[4][4][4];
    gemm_mainloop(X + (size_t)m0 * D_, W + (size_t)n0 * D_, acc);

    const int t = threadIdx.x;
    const int warp = t >> 5, l = t & 31, g = l >> 2, t4 = l & 3;
    const int wm = (warp >> 2) * 64, wn = (warp & 3) * 32;
#pragma unroll
    for (int mt = 0; mt < 4; mt++) {
        const int row = m0 + wm + mt * 16 + g;
        const int bb = row >> 11, s = row & 2047;
#pragma unroll
        for (int nt = 0; nt < 4; nt++) {
            const int col = n0 + wn + nt * 8 + 2 * t4;
            const int h = col >> 6, cl = col & 63;
            *(unsigned*)&O[(((size_t)bb * H_ + h) * S_ + s) * 64 + cl] =
                pk2(acc[mt][nt][0] * scale, acc[mt][nt][1] * scale);
            *(unsigned*)&O[(((size_t)bb * H_ + h) * S_ + (s + 8)) * 64 + cl] =
                pk2(acc[mt][nt][2] * scale, acc[mt][nt][3] * scale);
        }
    }
}

// ---------------------------------------------------------------------------
// Output projection + residual: out = ctx @ Wo^T + resid (fp32 out)
// ---------------------------------------------------------------------------
__global__ __launch_bounds__(256) void oproj_kernel(
    const float* __restrict__ resid, float* __restrict__ out)
{
    const int m0 = blockIdx.y * 128, n0 = blockIdx.x * 128;
    float acc[4][4][4];
    gemm_mainloop(g_ctx + (size_t)m0 * D_,
                  g_Wb + (size_t)3 * NW + (size_t)n0 * D_, acc);

    const int t = threadIdx.x;
    const int warp = t >> 5, l = t & 31, g = l >> 2, t4 = l & 3;
    const int wm = (warp >> 2) * 64, wn = (warp & 3) * 32;
#pragma unroll
    for (int mt = 0; mt < 4; mt++) {
        const int row = m0 + wm + mt * 16 + g;
#pragma unroll
        for (int nt = 0; nt < 4; nt++) {
            const int col = n0 + wn + nt * 8 + 2 * t4;
            float2 r0 = *(const float2*)&resid[(size_t)row * D_ + col];
            float2 r1 = *(const float2*)&resid[(size_t)(row + 8) * D_ + col];
            *(float2*)&out[(size_t)row * D_ + col] =
                make_float2(acc[mt][nt][0] + r0.x, acc[mt][nt][1] + r0.y);
            *(float2*)&out[(size_t)(row + 8) * D_ + col] =
                make_float2(acc[mt][nt][2] + r1.x, acc[mt][nt][3] + r1.y);
        }
    }
}

// ---------------------------------------------------------------------------
// Flash attention, bf16 m16n8k16 (unchanged from round 9).
// ---------------------------------------------------------------------------
__global__ __launch_bounds__(128) void attn_kernel(const int* __restrict__ sen_len)
{
    __shared__ unsigned Ks[64 * 36];    // [key][d-pairs]
    __shared__ unsigned VsT[64 * 36];   // [d][key-pairs]

    const int bh = blockIdx.y;
    const int b = bh >> 4, h = bh & 15;
    const int q0 = blockIdx.x * 64;
    const __nv_bfloat16* Qg = g_Qh + (size_t)bh * S_ * 64;
    const __nv_bfloat16* Kg = g_Kh + (size_t)bh * S_ * 64;
    const __nv_bfloat16* Vg = g_Vh + (size_t)bh * S_ * 64;
    const int sen = sen_len[b];
    const int kv_len = min(q0 + 64, sen);

    const int t = threadIdx.x;
    const int warp = t >> 5, l = t & 31, g = l >> 2, t4 = l & 3;
    const int wq = warp * 16;
    const int row0 = q0 + wq + g, row1 = row0 + 8;

    unsigned qa[4][4];
    {
        const __nv_bfloat16* Qr0 = Qg + (size_t)row0 * 64;
        const __nv_bfloat16* Qr1 = Qg + (size_t)row1 * 64;
#pragma unroll
        for (int kt = 0; kt < 4; kt++) {
            qa[kt][0] = *(const unsigned*)&Qr0[16 * kt + 2 * t4];
            qa[kt][1] = *(const unsigned*)&Qr1[16 * kt + 2 * t4];
            qa[kt][2] = *(const unsigned*)&Qr0[16 * kt + 8 + 2 * t4];
            qa[kt][3] = *(const unsigned*)&Qr1[16 * kt + 8 + 2 * t4];
        }
    }

    float oacc[8][4];
#pragma unroll
    for (int nt = 0; nt < 8; nt++)
#pragma unroll
        for (int i = 0; i < 4; i++) oacc[nt][i] = 0.f;
    float m0r = -1e30f, m1r = -1e30f, l0r = 0.f, l1r = 0.f;

    const int kp = t & 31, db0 = t >> 5;

    for (int k0 = 0; k0 < kv_len; k0 += 64) {
        __syncthreads();
#pragma unroll
        for (int it = 0; it < 4; it++) {
            const int f = t + it * 128;
            const int row = f >> 3, qd = f & 7;
            *(uint4*)&Ks[row * 36 + qd * 4] =
                *(const uint4*)&Kg[(size_t)(k0 + row) * 64 + qd * 8];
        }
#pragma unroll
        for (int it = 0; it < 2; it++) {
            const int db = db0 + it * 4;
            union { uint4 u; unsigned short s[8]; } r0, r1;
            r0.u = *(const uint4*)&Vg[(size_t)(k0 + 2 * kp) * 64 + db * 8];
            r1.u = *(const uint4*)&Vg[(size_t)(k0 + 2 * kp + 1) * 64 + db * 8];
#pragma unroll
            for (int j = 0; j < 8; j++)
                VsT[(db * 8 + j) * 36 + kp] =
                    (unsigned)r0.s[j] | ((unsigned)r1.s[j] << 16);
        }
        __syncthreads();

        float sacc[8][4];
#pragma unroll
        for (int nt = 0; nt < 8; nt++)
#pragma unroll
            for (int i = 0; i < 4; i++) sacc[nt][i] = 0.f;
#pragma unroll
        for (int kt = 0; kt < 4; kt++)
#pragma unroll
            for (int nt = 0; nt < 8; nt++) {
                unsigned bf[2];
                bf[0] = Ks[(nt * 8 + g) * 36 + kt * 8 + t4];
                bf[1] = Ks[(nt * 8 + g) * 36 + kt * 8 + t4 + 4];
                mma16(sacc[nt], qa[kt], bf);
            }

        if ((k0 + 63 > row0 - g) || (k0 + 64 > sen)) {
#pragma unroll
            for (int nt = 0; nt < 8; nt++) {
                const int c = k0 + nt * 8 + 2 * t4;
                if (c > row0     || c >= sen)     sacc[nt][0] = -1e9f;
                if (c + 1 > row0 || c + 1 >= sen) sacc[nt][1] = -1e9f;
                if (c > row1     || c >= sen)     sacc[nt][2] = -1e9f;
                if (c + 1 > row1 || c + 1 >= sen) sacc[nt][3] = -1e9f;
            }
        }

        float tm0 = -1e30f, tm1 = -1e30f;
#pragma unroll
        for (int nt = 0; nt < 8; nt++) {
            tm0 = fmaxf(tm0, fmaxf(sacc[nt][0], sacc[nt][1]));
            tm1 = fmaxf(tm1, fmaxf(sacc[nt][2], sacc[nt][3]));
        }
        tm0 = fmaxf(tm0, __shfl_xor_sync(0xffffffffu, tm0, 1));
        tm0 = fmaxf(tm0, __shfl_xor_sync(0xffffffffu, tm0, 2));
        tm1 = fmaxf(tm1, __shfl_xor_sync(0xffffffffu, tm1, 1));
        tm1 = fmaxf(tm1, __shfl_xor_sync(0xffffffffu, tm1, 2));
        const float mn0 = fmaxf(m0r, tm0), mn1 = fmaxf(m1r, tm1);
        const float a0 = ex2f(m0r - mn0), a1 = ex2f(m1r - mn1);
        m0r = mn0; m1r = mn1;
        float s0 = 0.f, s1 = 0.f;
#pragma unroll
        for (int nt = 0; nt < 8; nt++) {
            float p0 = ex2f(sacc[nt][0] - mn0);
            float p1 = ex2f(sacc[nt][1] - mn0);
            float p2 = ex2f(sacc[nt][2] - mn1);
            float p3 = ex2f(sacc[nt][3] - mn1);
            s0 += p0 + p1; s1 += p2 + p3;
            sacc[nt][0] = p0; sacc[nt][1] = p1; sacc[nt][2] = p2; sacc[nt][3] = p3;
            oacc[nt][0] *= a0; oacc[nt][1] *= a0;
            oacc[nt][2] *= a1; oacc[nt][3] *= a1;
        }
        s0 += __shfl_xor_sync(0xffffffffu, s0, 1);
        s0 += __shfl_xor_sync(0xffffffffu, s0, 2);
        s1 += __shfl_xor_sync(0xffffffffu, s1, 1);
        s1 += __shfl_xor_sync(0xffffffffu, s1, 2);
        l0r = l0r * a0 + s0;
        l1r = l1r * a1 + s1;

#pragma unroll
        for (int kt = 0; kt < 4; kt++) {
            unsigned pa[4];
            pa[0] = pk2(sacc[2 * kt][0],     sacc[2 * kt][1]);
            pa[1] = pk2(sacc[2 * kt][2],     sacc[2 * kt][3]);
            pa[2] = pk2(sacc[2 * kt + 1][0], sacc[2 * kt + 1][1]);
            pa[3] = pk2(sacc[2 * kt + 1][2], sacc[2 * kt + 1][3]);
#pragma unroll
            for (int nt = 0; nt < 8; nt++) {
                unsigned bf[2];
                bf[0] = VsT[(nt * 8 + g) * 36 + kt * 8 + t4];
                bf[1] = VsT[(nt * 8 + g) * 36 + kt * 8 + t4 + 4];
                mma16(oacc[nt], pa, bf);
            }
        }
    }

    const float inv0 = 1.f / l0r, inv1 = 1.f / l1r;
#pragma unroll
    for (int nt = 0; nt < 8; nt++) {
        const int cl = h * 64 + nt * 8 + 2 * t4;
        *(unsigned*)&g_ctx[((size_t)b * S_ + row0) * D_ + cl] =
            pk2(oacc[nt][0] * inv0, oacc[nt][1] * inv0);
        *(unsigned*)&g_ctx[((size_t)b * S_ + row1) * D_ + cl] =
            pk2(oacc[nt][2] * inv1, oacc[nt][3] * inv1);
    }
}

// ---------------------------------------------------------------------------
// LayerNorm (biased variance), in place. One block per 1024-elem row.
// ---------------------------------------------------------------------------
__global__ __launch_bounds__(256) void ln_kernel(
    float* __restrict__ out, const float* __restrict__ gamma,
    const float* __restrict__ beta)
{
    __shared__ float sbuf[8], ssbuf[8], red[2];
    const int row = blockIdx.x;
    float* p = out + (size_t)row * D_;
    const int t = threadIdx.x;

    float4 x = *(const float4*)&p[t * 4];
    float s  = x.x + x.y + x.z + x.w;
    float ss = x.x * x.x + x.y * x.y + x.z * x.z + x.w * x.w;
#pragma unroll
    for (int off = 16; off; off >>= 1) {
        s  += __shfl_xor_sync(0xffffffffu, s, off);
        ss += __shfl_xor_sync(0xffffffffu, ss, off);
    }
    if ((t & 31) == 0) { sbuf[t >> 5] = s; ssbuf[t >> 5] = ss; }
    __syncthreads();
    if (t == 0) {
        float S = 0.f, SS = 0.f;
        for (int i = 0; i < 8; i++) { S += sbuf[i]; SS += ssbuf[i]; }
        red[0] = S; red[1] = SS;
    }
    __syncthreads();
    float mean = red[0] * (1.f / 1024.f);
    float var  = red[1] * (1.f / 1024.f) - mean * mean;
    float inv  = rsqrtf(var + 1e-5f);

    float4 gg = *(const float4*)&gamma[t * 4];
    float4 bb = *(const float4*)&beta[t * 4];
    float4 y;
    y.x = (x.x - mean) * inv * gg.x + bb.x;
    y.y = (x.y - mean) * inv * gg.y + bb.y;
    y.z = (x.z - mean) * inv * gg.z + bb.z;
    y.w = (x.w - mean) * inv * gg.w + bb.w;
    *(float4*)&p[t * 4] = y;
}

// ---------------------------------------------------------------------------
extern "C" void kernel_launch(void* const* d_in, const int* in_sizes, int n_in,
                              void* d_out, int out_size)
{
    const float* q     = (const float*)d_in[0];
    const float* k     = (const float*)d_in[1];
    const float* v     = (const float*)d_in[2];
    const float* Wq    = (const float*)d_in[3];
    const float* Wk    = (const float*)d_in[4];
    const float* Wv    = (const float*)d_in[5];
    const float* Wo    = (const float*)d_in[6];
    const float* gamma = (const float*)d_in[7];
    const float* beta  = (const float*)d_in[8];
    const int*   sen   = (const int*)d_in[9];
    float* out = (float*)d_out;

    cudaFuncSetAttribute(proj_kernel,
                         cudaFuncAttributeMaxDynamicSharedMemorySize, GEMM_SMEM);
    cudaFuncSetAttribute(oproj_kernel,
                         cudaFuncAttributeMaxDynamicSharedMemorySize, GEMM_SMEM);

    conv_kernel<<<(3 * NX + 4 * NW) / (4 * 256), 256>>>(q, k, v, Wq, Wk, Wv, Wo);
    proj_kernel<<<dim3(D_ / 128, ROWS / 128, 3), 256, GEMM_SMEM>>>();
    attn_kernel<<<dim3(S_ / 64, B_ * H_), 128>>>(sen);
    oproj_kernel<<<dim3(D_ / 128, ROWS / 128), 256, GEMM_SMEM>>>(q, out);
    ln_kernel<<<ROWS, 256>>>(out, gamma, beta);
}

// round 13
// speedup vs baseline: 5.9801x; 1.0513x over previous
#include <cuda_runtime.h>
#include <cuda_bf16.h>

#define S_   2048
#define D_   1024
#define H_   16
#define B_   4
#define ROWS (B_*S_)
#define NX   (B_*S_*D_)     // 8388608 elems per q/k/v tensor
#define NW   (D_*D_)        // 1048576 elems per weight
#define LOG2E 1.4426950408889634f

// Scratch (allocation-free): module .bss, all bf16
__device__ __nv_bfloat16 g_Xb[(size_t)3*NX];   // q,k,v in bf16
__device__ __nv_bfloat16 g_Wb[(size_t)4*NW];   // Wq,Wk,Wv,Wo in bf16
__device__ __nv_bfloat16 g_Qh[(size_t)B_*H_*S_*64];
__device__ __nv_bfloat16 g_Kh[(size_t)B_*H_*S_*64];
__device__ __nv_bfloat16 g_Vh[(size_t)B_*H_*S_*64];
__device__ __nv_bfloat16 g_ctx[(size_t)ROWS*D_];

__device__ __forceinline__ float ex2f(float x) {
    float y; asm("ex2.approx.f32 %0, %1;" : "=f"(y) : "f"(x)); return y;
}
__device__ __forceinline__ unsigned pk2(float a, float b) {
    __nv_bfloat162 h = __float22bfloat162_rn(make_float2(a, b));
    return *reinterpret_cast<unsigned*>(&h);
}
__device__ __forceinline__ void mma16(float* c, const unsigned* a, const unsigned* b) {
    asm volatile(
        "mma.sync.aligned.m16n8k16.row.col.f32.bf16.bf16.f32 "
        "{%0,%1,%2,%3},{%4,%5,%6,%7},{%8,%9},{%0,%1,%2,%3};\n"
        : "+f"(c[0]), "+f"(c[1]), "+f"(c[2]), "+f"(c[3])
        : "r"(a[0]), "r"(a[1]), "r"(a[2]), "r"(a[3]), "r"(b[0]), "r"(b[1]));
}
__device__ __forceinline__ void ldsm4(unsigned* r, unsigned addr) {
    asm volatile("ldmatrix.sync.aligned.m8n8.x4.shared.b16 {%0,%1,%2,%3}, [%4];\n"
        : "=r"(r[0]), "=r"(r[1]), "=r"(r[2]), "=r"(r[3]) : "r"(addr));
}
__device__ __forceinline__ void cpa16(unsigned saddr, const void* g) {
    asm volatile("cp.async.cg.shared.global [%0], [%1], 16;\n"
        :: "r"(saddr), "l"(g));
}

// ---------------------------------------------------------------------------
// fp32 -> bf16 conversion pre-pass: q,k,v -> g_Xb; Wq,Wk,Wv,Wo -> g_Wb
// ---------------------------------------------------------------------------
__global__ __launch_bounds__(256) void conv_kernel(
    const float* __restrict__ q, const float* __restrict__ k, const float* __restrict__ v,
    const float* __restrict__ wq, const float* __restrict__ wk,
    const float* __restrict__ wv, const float* __restrict__ wo)
{
    size_t e = ((size_t)blockIdx.x * 256 + threadIdx.x) * 4;
    const float* src;
    __nv_bfloat16* dst;
    if (e < (size_t)3 * NX) {
        int s = (int)(e / NX);
        src = (s == 0) ? q : ((s == 1) ? k : v);
        dst = g_Xb + (size_t)s * NX;
        e -= (size_t)s * NX;
    } else {
        size_t r = e - (size_t)3 * NX;
        int s = (int)(r / NW);
        src = (s == 0) ? wq : ((s == 1) ? wk : ((s == 2) ? wv : wo));
        dst = g_Wb + (size_t)s * NW;
        e = r - (size_t)s * NW;
    }
    float4 x = *(const float4*)(src + e);
    *(__nv_bfloat162*)(dst + e)     = __float22bfloat162_rn(make_float2(x.x, x.y));
    *(__nv_bfloat162*)(dst + e + 2) = __float22bfloat162_rn(make_float2(x.z, x.w));
}

// ---------------------------------------------------------------------------
// Shared GEMM mainloop: C[128x128] = A[128xD] @ B[128xD]^T (NT), bf16 mma.
// 4-stage cp.async pipeline (wait_group 2 -> two-stage prefetch lead);
// pitch-20-word smem rows (ldmatrix phases conflict-free); per-kt fragment
// batch: all 24 LDSM issued before the 32 mmas (one exposed LDSM window/kt).
// 8 warps, 64x32 warp tiles, BK=32.
// Stage layout: [A 128*20 | B 128*20] words, stride 5120 words = 20480 B.
// ---------------------------------------------------------------------------
#define GEMM_SMEM (4 * 5120 * 4)   // 81920 B

__device__ __forceinline__ void gemm_mainloop(
    const __nv_bfloat16* __restrict__ Ablk,   // + m0*D_
    const __nv_bfloat16* __restrict__ Bblk,   // + n0*D_
    float acc[4][4][4])
{
    extern __shared__ unsigned smem_u[];
    const unsigned sbase = (unsigned)__cvta_generic_to_shared(smem_u);
    const int t = threadIdx.x;
    const int warp = t >> 5, l = t & 31;
    const int wm = (warp >> 2) * 64, wn = (warp & 3) * 32;

    // loaders: thread t -> row t>>2 (and +64), 16B chunk t&3
    const int lrow = t >> 2, lch = t & 3;
    const __nv_bfloat16* gA0 = Ablk + (size_t)lrow * D_ + lch * 8;
    const __nv_bfloat16* gA1 = gA0 + (size_t)64 * D_;
    const __nv_bfloat16* gB0 = Bblk + (size_t)lrow * D_ + lch * 8;
    const __nv_bfloat16* gB1 = gB0 + (size_t)64 * D_;
    const unsigned sA0 = sbase + (lrow * 20 + lch * 4) * 4;
    const unsigned sA1 = sA0 + 64 * 80;
    const unsigned sB0 = sA0 + 2560 * 4;
    const unsigned sB1 = sB0 + 64 * 80;

    // ldmatrix lane addressing (word offsets within a stage)
    const int arow = (l & 7) + 8 * ((l >> 3) & 1);   // A: m8-pair select
    const int acw  = 4 * (l >> 4);                   // A: k16-half select
    const int brow = (l & 7) + 8 * (l >> 4);         // B: n8-pair select
    const int bcw  = 4 * ((l >> 3) & 1);             // B: k16-half select

#pragma unroll
    for (int mt = 0; mt < 4; mt++)
#pragma unroll
        for (int nt = 0; nt < 4; nt++)
#pragma unroll
            for (int i = 0; i < 4; i++) acc[mt][nt][i] = 0.f;

    // prefetch stages 0..2
#pragma unroll
    for (int s = 0; s < 3; s++) {
        const int ko = s * 32;
        const unsigned so = s * 20480;
        cpa16(sA0 + so, gA0 + ko); cpa16(sA1 + so, gA1 + ko);
        cpa16(sB0 + so, gB0 + ko); cpa16(sB1 + so, gB1 + ko);
        asm volatile("cp.async.commit_group;\n" ::: "memory");
    }

#pragma unroll 1
    for (int kt = 0; kt < 32; kt++) {
        if (kt < 30)      asm volatile("cp.async.wait_group 2;\n" ::: "memory");
        else if (kt == 30) asm volatile("cp.async.wait_group 1;\n" ::: "memory");
        else              asm volatile("cp.async.wait_group 0;\n" ::: "memory");
        __syncthreads();
        if (kt + 3 < 32) {
            const int ko = (kt + 3) * 32;
            const unsigned so = ((kt + 3) & 3) * 20480;
            cpa16(sA0 + so, gA0 + ko); cpa16(sA1 + so, gA1 + ko);
            cpa16(sB0 + so, gB0 + ko); cpa16(sB1 + so, gB1 + ko);
            asm volatile("cp.async.commit_group;\n" ::: "memory");
        }
        const unsigned stA = sbase + (kt & 3) * 20480;
        const unsigned stB = stA + 2560 * 4;

        // batch ALL fragment loads for both ks-steps first
        unsigned af[2][4][4], bq[2][2][4];
#pragma unroll
        for (int ks = 0; ks < 2; ks++) {
#pragma unroll
            for (int mt = 0; mt < 4; mt++)
                ldsm4(af[ks][mt],
                      stA + ((wm + mt * 16 + arow) * 20 + ks * 8 + acw) * 4);
#pragma unroll
            for (int p = 0; p < 2; p++)
                ldsm4(bq[ks][p],
                      stB + ((wn + p * 16 + brow) * 20 + ks * 8 + bcw) * 4);
        }
        // then the full mma stream
#pragma unroll
        for (int ks = 0; ks < 2; ks++)
#pragma unroll
            for (int mt = 0; mt < 4; mt++)
#pragma unroll
                for (int nt = 0; nt < 4; nt++) {
                    unsigned bfr[2] = { bq[ks][nt >> 1][(nt & 1) * 2],
                                        bq[ks][nt >> 1][(nt & 1) * 2 + 1] };
                    mma16(acc[mt][nt], af[ks][mt], bfr);
                }
    }
}

// ---------------------------------------------------------------------------
// QKV projection: O = X @ W^T; epilogue remaps to [b,h,s,64] bf16,
// Q folds 0.125*log2(e).
// ---------------------------------------------------------------------------
__global__ __launch_bounds__(256, 2) void proj_kernel()
{
    const int z = blockIdx.z;
    const __nv_bfloat16* X = g_Xb + (size_t)z * NX;
    const __nv_bfloat16* W = g_Wb + (size_t)z * NW;
    __nv_bfloat16* O = (z == 0) ? g_Qh : ((z == 1) ? g_Kh : g_Vh);
    const float scale = (z == 0) ? 0.125f * LOG2E : 1.0f;

    const int m0 = blockIdx.y * 128, n0 = blockIdx.x * 128;
    float acc[4][4][4];
    gemm_mainloop(X + (size_t)m0 * D_, W + (size_t)n0 * D_, acc);

    const int t = threadIdx.x;
    const int warp = t >> 5, l = t & 31, g = l >> 2, t4 = l & 3;
    const int wm = (warp >> 2) * 64, wn = (warp & 3) * 32;
#pragma unroll
    for (int mt = 0; mt < 4; mt++) {
        const int row = m0 + wm + mt * 16 + g;
        const int bb = row >> 11, s = row & 2047;
#pragma unroll
        for (int nt = 0; nt < 4; nt++) {
            const int col = n0 + wn + nt * 8 + 2 * t4;
            const int h = col >> 6, cl = col & 63;
            *(unsigned*)&O[(((size_t)bb * H_ + h) * S_ + s) * 64 + cl] =
                pk2(acc[mt][nt][0] * scale, acc[mt][nt][1] * scale);
            *(unsigned*)&O[(((size_t)bb * H_ + h) * S_ + (s + 8)) * 64 + cl] =
                pk2(acc[mt][nt][2] * scale, acc[mt][nt][3] * scale);
        }
    }
}

// ---------------------------------------------------------------------------
// Output projection + residual: out = ctx @ Wo^T + resid (fp32 out)
// ---------------------------------------------------------------------------
__global__ __launch_bounds__(256, 2) void oproj_kernel(
    const float* __restrict__ resid, float* __restrict__ out)
{
    const int m0 = blockIdx.y * 128, n0 = blockIdx.x * 128;
    float acc[4][4][4];
    gemm_mainloop(g_ctx + (size_t)m0 * D_,
                  g_Wb + (size_t)3 * NW + (size_t)n0 * D_, acc);

    const int t = threadIdx.x;
    const int warp = t >> 5, l = t & 31, g = l >> 2, t4 = l & 3;
    const int wm = (warp >> 2) * 64, wn = (warp & 3) * 32;
#pragma unroll
    for (int mt = 0; mt < 4; mt++) {
        const int row = m0 + wm + mt * 16 + g;
#pragma unroll
        for (int nt = 0; nt < 4; nt++) {
            const int col = n0 + wn + nt * 8 + 2 * t4;
            float2 r0 = *(const float2*)&resid[(size_t)row * D_ + col];
            float2 r1 = *(const float2*)&resid[(size_t)(row + 8) * D_ + col];
            *(float2*)&out[(size_t)row * D_ + col] =
                make_float2(acc[mt][nt][0] + r0.x, acc[mt][nt][1] + r0.y);
            *(float2*)&out[(size_t)(row + 8) * D_ + col] =
                make_float2(acc[mt][nt][2] + r1.x, acc[mt][nt][3] + r1.y);
        }
    }
}

// ---------------------------------------------------------------------------
// Flash attention, bf16 m16n8k16 (unchanged from round 10).
// ---------------------------------------------------------------------------
__global__ __launch_bounds__(128) void attn_kernel(const int* __restrict__ sen_len)
{
    __shared__ unsigned Ks[64 * 36];    // [key][d-pairs]
    __shared__ unsigned VsT[64 * 36];   // [d][key-pairs]

    const int bh = blockIdx.y;
    const int b = bh >> 4, h = bh & 15;
    const int q0 = blockIdx.x * 64;
    const __nv_bfloat16* Qg = g_Qh + (size_t)bh * S_ * 64;
    const __nv_bfloat16* Kg = g_Kh + (size_t)bh * S_ * 64;
    const __nv_bfloat16* Vg = g_Vh + (size_t)bh * S_ * 64;
    const int sen = sen_len[b];
    const int kv_len = min(q0 + 64, sen);

    const int t = threadIdx.x;
    const int warp = t >> 5, l = t & 31, g = l >> 2, t4 = l & 3;
    const int wq = warp * 16;
    const int row0 = q0 + wq + g, row1 = row0 + 8;

    unsigned qa[4][4];
    {
        const __nv_bfloat16* Qr0 = Qg + (size_t)row0 * 64;
        const __nv_bfloat16* Qr1 = Qg + (size_t)row1 * 64;
#pragma unroll
        for (int kt = 0; kt < 4; kt++) {
            qa[kt][0] = *(const unsigned*)&Qr0[16 * kt + 2 * t4];
            qa[kt][1] = *(const unsigned*)&Qr1[16 * kt + 2 * t4];
            qa[kt][2] = *(const unsigned*)&Qr0[16 * kt + 8 + 2 * t4];
            qa[kt][3] = *(const unsigned*)&Qr1[16 * kt + 8 + 2 * t4];
        }
    }

    float oacc[8][4];
#pragma unroll
    for (int nt = 0; nt < 8; nt++)
#pragma unroll
        for (int i = 0; i < 4; i++) oacc[nt][i] = 0.f;
    float m0r = -1e30f, m1r = -1e30f, l0r = 0.f, l1r = 0.f;

    const int kp = t & 31, db0 = t >> 5;

    for (int k0 = 0; k0 < kv_len; k0 += 64) {
        __syncthreads();
#pragma unroll
        for (int it = 0; it < 4; it++) {
            const int f = t + it * 128;
            const int row = f >> 3, qd = f & 7;
            *(uint4*)&Ks[row * 36 + qd * 4] =
                *(const uint4*)&Kg[(size_t)(k0 + row) * 64 + qd * 8];
        }
#pragma unroll
        for (int it = 0; it < 2; it++) {
            const int db = db0 + it * 4;
            union { uint4 u; unsigned short s[8]; } r0, r1;
            r0.u = *(const uint4*)&Vg[(size_t)(k0 + 2 * kp) * 64 + db * 8];
            r1.u = *(const uint4*)&Vg[(size_t)(k0 + 2 * kp + 1) * 64 + db * 8];
#pragma unroll
            for (int j = 0; j < 8; j++)
                VsT[(db * 8 + j) * 36 + kp] =
                    (unsigned)r0.s[j] | ((unsigned)r1.s[j] << 16);
        }
        __syncthreads();

        float sacc[8][4];
#pragma unroll
        for (int nt = 0; nt < 8; nt++)
#pragma unroll
            for (int i = 0; i < 4; i++) sacc[nt][i] = 0.f;
#pragma unroll
        for (int kt = 0; kt < 4; kt++)
#pragma unroll
            for (int nt = 0; nt < 8; nt++) {
                unsigned bf[2];
                bf[0] = Ks[(nt * 8 + g) * 36 + kt * 8 + t4];
                bf[1] = Ks[(nt * 8 + g) * 36 + kt * 8 + t4 + 4];
                mma16(sacc[nt], qa[kt], bf);
            }

        if ((k0 + 63 > row0 - g) || (k0 + 64 > sen)) {
#pragma unroll
            for (int nt = 0; nt < 8; nt++) {
                const int c = k0 + nt * 8 + 2 * t4;
                if (c > row0     || c >= sen)     sacc[nt][0] = -1e9f;
                if (c + 1 > row0 || c + 1 >= sen) sacc[nt][1] = -1e9f;
                if (c > row1     || c >= sen)     sacc[nt][2] = -1e9f;
                if (c + 1 > row1 || c + 1 >= sen) sacc[nt][3] = -1e9f;
            }
        }

        float tm0 = -1e30f, tm1 = -1e30f;
#pragma unroll
        for (int nt = 0; nt < 8; nt++) {
            tm0 = fmaxf(tm0, fmaxf(sacc[nt][0], sacc[nt][1]));
            tm1 = fmaxf(tm1, fmaxf(sacc[nt][2], sacc[nt][3]));
        }
        tm0 = fmaxf(tm0, __shfl_xor_sync(0xffffffffu, tm0, 1));
        tm0 = fmaxf(tm0, __shfl_xor_sync(0xffffffffu, tm0, 2));
        tm1 = fmaxf(tm1, __shfl_xor_sync(0xffffffffu, tm1, 1));
        tm1 = fmaxf(tm1, __shfl_xor_sync(0xffffffffu, tm1, 2));
        const float mn0 = fmaxf(m0r, tm0), mn1 = fmaxf(m1r, tm1);
        const float a0 = ex2f(m0r - mn0), a1 = ex2f(m1r - mn1);
        m0r = mn0; m1r = mn1;
        float s0 = 0.f, s1 = 0.f;
#pragma unroll
        for (int nt = 0; nt < 8; nt++) {
            float p0 = ex2f(sacc[nt][0] - mn0);
            float p1 = ex2f(sacc[nt][1] - mn0);
            float p2 = ex2f(sacc[nt][2] - mn1);
            float p3 = ex2f(sacc[nt][3] - mn1);
            s0 += p0 + p1; s1 += p2 + p3;
            sacc[nt][0] = p0; sacc[nt][1] = p1; sacc[nt][2] = p2; sacc[nt][3] = p3;
            oacc[nt][0] *= a0; oacc[nt][1] *= a0;
            oacc[nt][2] *= a1; oacc[nt][3] *= a1;
        }
        s0 += __shfl_xor_sync(0xffffffffu, s0, 1);
        s0 += __shfl_xor_sync(0xffffffffu, s0, 2);
        s1 += __shfl_xor_sync(0xffffffffu, s1, 1);
        s1 += __shfl_xor_sync(0xffffffffu, s1, 2);
        l0r = l0r * a0 + s0;
        l1r = l1r * a1 + s1;

#pragma unroll
        for (int kt = 0; kt < 4; kt++) {
            unsigned pa[4];
            pa[0] = pk2(sacc[2 * kt][0],     sacc[2 * kt][1]);
            pa[1] = pk2(sacc[2 * kt][2],     sacc[2 * kt][3]);
            pa[2] = pk2(sacc[2 * kt + 1][0], sacc[2 * kt + 1][1]);
            pa[3] = pk2(sacc[2 * kt + 1][2], sacc[2 * kt + 1][3]);
#pragma unroll
            for (int nt = 0; nt < 8; nt++) {
                unsigned bf[2];
                bf[0] = VsT[(nt * 8 + g) * 36 + kt * 8 + t4];
                bf[1] = VsT[(nt * 8 + g) * 36 + kt * 8 + t4 + 4];
                mma16(oacc[nt], pa, bf);
            }
        }
    }

    const float inv0 = 1.f / l0r, inv1 = 1.f / l1r;
#pragma unroll
    for (int nt = 0; nt < 8; nt++) {
        const int cl = h * 64 + nt * 8 + 2 * t4;
        *(unsigned*)&g_ctx[((size_t)b * S_ + row0) * D_ + cl] =
            pk2(oacc[nt][0] * inv0, oacc[nt][1] * inv0);
        *(unsigned*)&g_ctx[((size_t)b * S_ + row1) * D_ + cl] =
            pk2(oacc[nt][2] * inv1, oacc[nt][3] * inv1);
    }
}

// ---------------------------------------------------------------------------
// LayerNorm (biased variance), in place. One block per 1024-elem row.
// ---------------------------------------------------------------------------
__global__ __launch_bounds__(256) void ln_kernel(
    float* __restrict__ out, const float* __restrict__ gamma,
    const float* __restrict__ beta)
{
    __shared__ float sbuf[8], ssbuf[8], red[2];
    const int row = blockIdx.x;
    float* p = out + (size_t)row * D_;
    const int t = threadIdx.x;

    float4 x = *(const float4*)&p[t * 4];
    float s  = x.x + x.y + x.z + x.w;
    float ss = x.x * x.x + x.y * x.y + x.z * x.z + x.w * x.w;
#pragma unroll
    for (int off = 16; off; off >>= 1) {
        s  += __shfl_xor_sync(0xffffffffu, s, off);
        ss += __shfl_xor_sync(0xffffffffu, ss, off);
    }
    if ((t & 31) == 0) { sbuf[t >> 5] = s; ssbuf[t >> 5] = ss; }
    __syncthreads();
    if (t == 0) {
        float S = 0.f, SS = 0.f;
        for (int i = 0; i < 8; i++) { S += sbuf[i]; SS += ssbuf[i]; }
        red[0] = S; red[1] = SS;
    }
    __syncthreads();
    float mean = red[0] * (1.f / 1024.f);
    float var  = red[1] * (1.f / 1024.f) - mean * mean;
    float inv  = rsqrtf(var + 1e-5f);

    float4 gg = *(const float4*)&gamma[t * 4];
    float4 bb = *(const float4*)&beta[t * 4];
    float4 y;
    y.x = (x.x - mean) * inv * gg.x + bb.x;
    y.y = (x.y - mean) * inv * gg.y + bb.y;
    y.z = (x.z - mean) * inv * gg.z + bb.z;
    y.w = (x.w - mean) * inv * gg.w + bb.w;
    *(float4*)&p[t * 4] = y;
}

// ---------------------------------------------------------------------------
extern "C" void kernel_launch(void* const* d_in, const int* in_sizes, int n_in,
                              void* d_out, int out_size)
{
    const float* q     = (const float*)d_in[0];
    const float* k     = (const float*)d_in[1];
    const float* v     = (const float*)d_in[2];
    const float* Wq    = (const float*)d_in[3];
    const float* Wk    = (const float*)d_in[4];
    const float* Wv    = (const float*)d_in[5];
    const float* Wo    = (const float*)d_in[6];
    const float* gamma = (const float*)d_in[7];
    const float* beta  = (const float*)d_in[8];
    const int*   sen   = (const int*)d_in[9];
    float* out = (float*)d_out;

    cudaFuncSetAttribute(proj_kernel,
                         cudaFuncAttributeMaxDynamicSharedMemorySize, GEMM_SMEM);
    cudaFuncSetAttribute(oproj_kernel,
                         cudaFuncAttributeMaxDynamicSharedMemorySize, GEMM_SMEM);

    conv_kernel<<<(3 * NX + 4 * NW) / (4 * 256), 256>>>(q, k, v, Wq, Wk, Wv, Wo);
    proj_kernel<<<dim3(D_ / 128, ROWS / 128, 3), 256, GEMM_SMEM>>>();
    attn_kernel<<<dim3(S_ / 64, B_ * H_), 128>>>(sen);
    oproj_kernel<<<dim3(D_ / 128, ROWS / 128), 256, GEMM_SMEM>>>(q, out);
    ln_kernel<<<ROWS, 256>>>(out, gamma, beta);
}